// round 7
// baseline (speedup 1.0000x reference)
#include <cuda_runtime.h>
#include <math.h>
#include <stdint.h>

#define NEGINF -1000000.0f

// Problem constants
#define BATCH 8
#define SEQ   2048
#define EMB   512
#define BSZ   (BATCH * SEQ)

// Scratch: Q, K, V projections (fp32). __device__ globals (no allocs allowed).
__device__ float g_Q[(size_t)BSZ * EMB];
__device__ float g_K[(size_t)BSZ * EMB];
__device__ float g_V[(size_t)BSZ * EMB];

// Tiling: block 128x128, BK=16 double-buffered, 4 warps (2x2), warp tile 64x64.
#define BM 128
#define BN 128
#define BK 16
#define PAD 4
#define NTHREADS 128

__device__ __forceinline__ uint32_t f2tf(float f) {
    uint32_t r;
    asm("cvt.rna.tf32.f32 %0, %1;" : "=r"(r) : "f"(f));
    return r;
}

__device__ __forceinline__ void mma_tf32(float (&d)[4], const uint32_t (&a)[4],
                                         const uint32_t (&b)[2]) {
    asm volatile(
        "mma.sync.aligned.m16n8k8.row.col.f32.tf32.tf32.f32 "
        "{%0,%1,%2,%3}, {%4,%5,%6,%7}, {%8,%9}, {%0,%1,%2,%3};\n"
        : "+f"(d[0]), "+f"(d[1]), "+f"(d[2]), "+f"(d[3])
        : "r"(a[0]), "r"(a[1]), "r"(a[2]), "r"(a[3]), "r"(b[0]), "r"(b[1]));
}

// Compute one BK=16 chunk: warp tile 64x64 (Mf=4, Nf=8).
#define COMPUTE_CHUNK(AsBuf, BsBuf)                                          \
    do {                                                                     \
        _Pragma("unroll")                                                    \
        for (int ks = 0; ks < 2; ks++) {                                     \
            int kk = ks * 8;                                                 \
            uint32_t af[4][4], bf[8][2];                                     \
            _Pragma("unroll")                                                \
            for (int mi = 0; mi < 4; mi++) {                                 \
                int m = wm * 64 + mi * 16 + gid;                             \
                af[mi][0] = (AsBuf)[kk + tig][m];                            \
                af[mi][1] = (AsBuf)[kk + tig][m + 8];                        \
                af[mi][2] = (AsBuf)[kk + tig + 4][m];                        \
                af[mi][3] = (AsBuf)[kk + tig + 4][m + 8];                    \
            }                                                                \
            _Pragma("unroll")                                                \
            for (int ni = 0; ni < 8; ni++) {                                 \
                int n = wn * 64 + ni * 8 + gid;                              \
                bf[ni][0] = (BsBuf)[kk + tig][n];                            \
                bf[ni][1] = (BsBuf)[kk + tig + 4][n];                        \
            }                                                                \
            _Pragma("unroll")                                                \
            for (int mi = 0; mi < 4; mi++)                                   \
                _Pragma("unroll")                                            \
                for (int ni = 0; ni < 8; ni++)                               \
                    mma_tf32(acc[mi][ni], af[mi], bf[ni]);                   \
        }                                                                    \
    } while (0)

// Staging (128 threads):
//  A-style (transpose): thread t loads the 16 k-values of row (base+t),
//  stores As[k][t].
//  B-style (direct): thread t loads 16 contiguous n-values of k-row (t>>3),
//  stores a uint4 row segment.
#define LDG_AROW(dst, src, row, lds, k0)                                      \
    do {                                                                      \
        _Pragma("unroll")                                                     \
        for (int p = 0; p < 4; p++)                                           \
            dst[p] = *(const float4*)&src[(size_t)(row) * (lds) + (k0) + p * 4]; \
    } while (0)
#define STS_AROW(buf, arr, col)                                               \
    do {                                                                      \
        _Pragma("unroll")                                                     \
        for (int p = 0; p < 4; p++) {                                         \
            buf[p * 4 + 0][col] = f2tf(arr[p].x);                             \
            buf[p * 4 + 1][col] = f2tf(arr[p].y);                             \
            buf[p * 4 + 2][col] = f2tf(arr[p].z);                             \
            buf[p * 4 + 3][col] = f2tf(arr[p].w);                             \
        }                                                                     \
    } while (0)
#define LDG_BROW(dst, src, k0, ldb, n0)                                       \
    do {                                                                      \
        _Pragma("unroll")                                                     \
        for (int p = 0; p < 4; p++)                                           \
            dst[p] = *(const float4*)&src[(size_t)((k0) + (tid >> 3)) * (ldb) + \
                                          (n0) + (tid & 7) * 16 + p * 4];     \
    } while (0)
#define STS_BROW(buf, arr)                                                    \
    do {                                                                      \
        _Pragma("unroll")                                                     \
        for (int p = 0; p < 4; p++) {                                         \
            uint4 u = make_uint4(f2tf(arr[p].x), f2tf(arr[p].y),              \
                                 f2tf(arr[p].z), f2tf(arr[p].w));             \
            *(uint4*)&buf[tid >> 3][(tid & 7) * 16 + p * 4] = u;              \
        }                                                                     \
    } while (0)

// ---------------------------------------------------------------------------
// Kernel 1: projections. C = alpha * A[M,512] @ W[512,512]; z picks Q/K/V.
// ---------------------------------------------------------------------------
__global__ __launch_bounds__(NTHREADS, 2)
void proj_kernel(const float* __restrict__ Xq, const float* __restrict__ Xk,
                 const float* __restrict__ Xv, const float* __restrict__ Wq,
                 const float* __restrict__ Wk, const float* __restrict__ Wv,
                 float inv_scale)
{
    const float* A; const float* W; float* C; float alpha;
    int z = blockIdx.z;
    if (z == 0)      { A = Xq; W = Wq; C = g_Q; alpha = inv_scale; }
    else if (z == 1) { A = Xk; W = Wk; C = g_K; alpha = inv_scale; }
    else             { A = Xv; W = Wv; C = g_V; alpha = 1.0f; }

    const int K = 512, N = 512;

    __shared__ uint32_t As[2][BK][BM + PAD];
    __shared__ uint32_t Bs[2][BK][BN + PAD];

    int tid = threadIdx.x;
    int wid = tid >> 5, lane = tid & 31;
    int gid = lane >> 2, tig = lane & 3;
    int wm = wid >> 1, wn = wid & 1;
    int m0 = blockIdx.y * BM, n0 = blockIdx.x * BN;

    float acc[4][8][4];
#pragma unroll
    for (int i = 0; i < 4; i++)
#pragma unroll
        for (int j = 0; j < 8; j++)
#pragma unroll
            for (int r = 0; r < 4; r++) acc[i][j][r] = 0.f;

    float4 ra[4], rb[4];

    LDG_AROW(ra, A, m0 + tid, K, 0);
    LDG_BROW(rb, W, 0, N, n0);
    STS_AROW(As[0], ra, tid);
    STS_BROW(Bs[0], rb);
    __syncthreads();

    const int iters = K / BK;
    for (int it = 0; it < iters; it++) {
        int cur = it & 1;
        bool more = (it + 1 < iters);
        if (more) {
            LDG_AROW(ra, A, m0 + tid, K, (it + 1) * BK);
            LDG_BROW(rb, W, (it + 1) * BK, N, n0);
        }
        COMPUTE_CHUNK(As[cur], Bs[cur]);
        if (more) {
            STS_AROW(As[cur ^ 1], ra, tid);
            STS_BROW(Bs[cur ^ 1], rb);
        }
        __syncthreads();
    }

#pragma unroll
    for (int mi = 0; mi < 4; mi++) {
        int r = m0 + wm * 64 + mi * 16 + gid;
#pragma unroll
        for (int ni = 0; ni < 8; ni++) {
            int c = n0 + wn * 64 + ni * 8 + tig * 2;
            *(float2*)&C[(size_t)r * N + c] =
                make_float2(acc[mi][ni][0] * alpha, acc[mi][ni][1] * alpha);
            *(float2*)&C[(size_t)(r + 8) * N + c] =
                make_float2(acc[mi][ni][2] * alpha, acc[mi][ni][3] * alpha);
        }
    }
}

// ---------------------------------------------------------------------------
// Kernel 2: masked scores. logits = Q Kt, NEGINF where mask==0. Per batch.
// ---------------------------------------------------------------------------
__global__ __launch_bounds__(NTHREADS, 2)
void scores_kernel(const int* __restrict__ mask, float* __restrict__ out_p)
{
    const int K = 512;
    int b = blockIdx.z;
    const float* Qb = g_Q + (size_t)b * SEQ * EMB;
    const float* Kb = g_K + (size_t)b * SEQ * EMB;
    const int*  Mb  = mask + (size_t)b * SEQ * SEQ;
    float*      Cb  = out_p + (size_t)b * SEQ * SEQ;

    __shared__ uint32_t As[2][BK][BM + PAD];
    __shared__ uint32_t Bs[2][BK][BN + PAD];

    int tid = threadIdx.x;
    int wid = tid >> 5, lane = tid & 31;
    int gid = lane >> 2, tig = lane & 3;
    int wm = wid >> 1, wn = wid & 1;
    int m0 = blockIdx.y * BM, n0 = blockIdx.x * BN;

    float acc[4][8][4];
#pragma unroll
    for (int i = 0; i < 4; i++)
#pragma unroll
        for (int j = 0; j < 8; j++)
#pragma unroll
            for (int r = 0; r < 4; r++) acc[i][j][r] = 0.f;

    float4 ra[4], rb[4];

    LDG_AROW(ra, Qb, m0 + tid, K, 0);
    LDG_AROW(rb, Kb, n0 + tid, K, 0);
    STS_AROW(As[0], ra, tid);
    STS_AROW(Bs[0], rb, tid);
    __syncthreads();

    const int iters = K / BK;
    for (int it = 0; it < iters; it++) {
        int cur = it & 1;
        bool more = (it + 1 < iters);
        if (more) {
            LDG_AROW(ra, Qb, m0 + tid, K, (it + 1) * BK);
            LDG_AROW(rb, Kb, n0 + tid, K, (it + 1) * BK);
        }
        COMPUTE_CHUNK(As[cur], Bs[cur]);
        if (more) {
            STS_AROW(As[cur ^ 1], ra, tid);
            STS_AROW(Bs[cur ^ 1], rb, tid);
        }
        __syncthreads();
    }

#pragma unroll
    for (int mi = 0; mi < 4; mi++) {
        int r = m0 + wm * 64 + mi * 16 + gid;
#pragma unroll
        for (int ni = 0; ni < 8; ni++) {
            int c = n0 + wn * 64 + ni * 8 + tig * 2;
            size_t o0 = (size_t)r * SEQ + c;
            size_t o1 = (size_t)(r + 8) * SEQ + c;
            int2 mv0 = *(const int2*)&Mb[o0];
            int2 mv1 = *(const int2*)&Mb[o1];
            *(float2*)&Cb[o0] = make_float2(mv0.x ? acc[mi][ni][0] : NEGINF,
                                            mv0.y ? acc[mi][ni][1] : NEGINF);
            *(float2*)&Cb[o1] = make_float2(mv1.x ? acc[mi][ni][2] : NEGINF,
                                            mv1.y ? acc[mi][ni][3] : NEGINF);
        }
    }
}

// ---------------------------------------------------------------------------
// Kernel 3: row softmax (in place). Masked = NEGINF -> exactly 0.
// ---------------------------------------------------------------------------
__global__ __launch_bounds__(256)
void softmax_kernel(float* __restrict__ P)
{
    float* prow = P + (size_t)blockIdx.x * SEQ;
    int tid = threadIdx.x;
    int lane = tid & 31, warp = tid >> 5;
    __shared__ float red[8];

    float4 v0 = ((const float4*)prow)[tid];
    float4 v1 = ((const float4*)prow)[tid + 256];
    float x[8] = {v0.x, v0.y, v0.z, v0.w, v1.x, v1.y, v1.z, v1.w};

    float m = x[0];
#pragma unroll
    for (int i = 1; i < 8; i++) m = fmaxf(m, x[i]);
#pragma unroll
    for (int o = 16; o > 0; o >>= 1) m = fmaxf(m, __shfl_xor_sync(0xFFFFFFFFu, m, o));
    if (lane == 0) red[warp] = m;
    __syncthreads();
    m = red[0];
#pragma unroll
    for (int i = 1; i < 8; i++) m = fmaxf(m, red[i]);

    if (m == NEGINF) {  // fully masked row
        float4 zz = make_float4(0.f, 0.f, 0.f, 0.f);
        ((float4*)prow)[tid] = zz;
        ((float4*)prow)[tid + 256] = zz;
        return;
    }

    float e[8], s = 0.f;
#pragma unroll
    for (int i = 0; i < 8; i++) { e[i] = __expf(x[i] - m); s += e[i]; }
#pragma unroll
    for (int o = 16; o > 0; o >>= 1) s += __shfl_xor_sync(0xFFFFFFFFu, s, o);
    __syncthreads();
    if (lane == 0) red[warp] = s;
    __syncthreads();
    s = 0.f;
#pragma unroll
    for (int i = 0; i < 8; i++) s += red[i];
    float inv = 1.0f / s;

    ((float4*)prow)[tid]       = make_float4(e[0] * inv, e[1] * inv, e[2] * inv, e[3] * inv);
    ((float4*)prow)[tid + 256] = make_float4(e[4] * inv, e[5] * inv, e[6] * inv, e[7] * inv);
}

// ---------------------------------------------------------------------------
// Kernel 4: z = P @ V per batch. M=2048, N=512, K=2048.
// ---------------------------------------------------------------------------
__global__ __launch_bounds__(NTHREADS, 2)
void pv_kernel(const float* __restrict__ P, float* __restrict__ out_z)
{
    const int K = SEQ, N = EMB;
    int b = blockIdx.z;
    const float* Ab = P + (size_t)b * SEQ * SEQ;
    const float* Vb = g_V + (size_t)b * SEQ * EMB;
    float*       Cb = out_z + (size_t)b * SEQ * EMB;

    __shared__ uint32_t As[2][BK][BM + PAD];
    __shared__ uint32_t Bs[2][BK][BN + PAD];

    int tid = threadIdx.x;
    int wid = tid >> 5, lane = tid & 31;
    int gid = lane >> 2, tig = lane & 3;
    int wm = wid >> 1, wn = wid & 1;
    int m0 = blockIdx.y * BM, n0 = blockIdx.x * BN;

    float acc[4][8][4];
#pragma unroll
    for (int i = 0; i < 4; i++)
#pragma unroll
        for (int j = 0; j < 8; j++)
#pragma unroll
            for (int r = 0; r < 4; r++) acc[i][j][r] = 0.f;

    float4 ra[4], rb[4];

    LDG_AROW(ra, Ab, m0 + tid, K, 0);
    LDG_BROW(rb, Vb, 0, N, n0);
    STS_AROW(As[0], ra, tid);
    STS_BROW(Bs[0], rb);
    __syncthreads();

    const int iters = K / BK;
    for (int it = 0; it < iters; it++) {
        int cur = it & 1;
        bool more = (it + 1 < iters);
        if (more) {
            LDG_AROW(ra, Ab, m0 + tid, K, (it + 1) * BK);
            LDG_BROW(rb, Vb, (it + 1) * BK, N, n0);
        }
        COMPUTE_CHUNK(As[cur], Bs[cur]);
        if (more) {
            STS_AROW(As[cur ^ 1], ra, tid);
            STS_BROW(Bs[cur ^ 1], rb);
        }
        __syncthreads();
    }

#pragma unroll
    for (int mi = 0; mi < 4; mi++) {
        int r = m0 + wm * 64 + mi * 16 + gid;
#pragma unroll
        for (int ni = 0; ni < 8; ni++) {
            int c = n0 + wn * 64 + ni * 8 + tig * 2;
            *(float2*)&Cb[(size_t)r * N + c] = make_float2(acc[mi][ni][0], acc[mi][ni][1]);
            *(float2*)&Cb[(size_t)(r + 8) * N + c] = make_float2(acc[mi][ni][2], acc[mi][ni][3]);
        }
    }
}

// ---------------------------------------------------------------------------
// Launch. Inputs: Xin_q, Xin_k, Xin_v, mask, Wq, Wk, Wv.
// Output: z [8,2048,512] then attn_p [8,2048,2048], fp32.
// ---------------------------------------------------------------------------
extern "C" void kernel_launch(void* const* d_in, const int* in_sizes, int n_in,
                              void* d_out, int out_size)
{
    const float* Xq = (const float*)d_in[0];
    const float* Xk = (const float*)d_in[1];
    const float* Xv = (const float*)d_in[2];
    const int*   mk = (const int*)d_in[3];
    const float* Wq = (const float*)d_in[4];
    const float* Wk = (const float*)d_in[5];
    const float* Wv = (const float*)d_in[6];

    float* out_z = (float*)d_out;
    float* out_p = out_z + (size_t)BATCH * SEQ * EMB;

    const float inv_scale = 0.21022410381342864f;  // 1/512^(1/4)

    proj_kernel<<<dim3(EMB / BN, BSZ / BM, 3), NTHREADS>>>(Xq, Xk, Xv, Wq, Wk, Wv, inv_scale);
    scores_kernel<<<dim3(SEQ / BN, SEQ / BM, BATCH), NTHREADS>>>(mk, out_p);
    softmax_kernel<<<BSZ, 256>>>(out_p);
    pv_kernel<<<dim3(EMB / BN, SEQ / BM, BATCH), NTHREADS>>>(out_p, out_z);
}

// round 8
// speedup vs baseline: 1.6735x; 1.6735x over previous
#include <cuda_runtime.h>
#include <math.h>
#include <stdint.h>

#define NEGINF -1000000.0f

// Problem constants
#define BATCH 8
#define SEQ   2048
#define EMB   512
#define BSZ   (BATCH * SEQ)

// Scratch (no allocs allowed). Values stored as tf32-rounded fp32 bit patterns.
__device__ float g_Q[(size_t)BSZ * EMB];
__device__ float g_K[(size_t)BSZ * EMB];
__device__ float g_V[(size_t)BSZ * EMB];

#define BM 128
#define BN 128
#define BK 16

__device__ __forceinline__ uint32_t f2tf(float f) {
    uint32_t r;
    asm("cvt.rna.tf32.f32 %0, %1;" : "=r"(r) : "f"(f));
    return r;
}
__device__ __forceinline__ float f2tf_f(float f) { return __uint_as_float(f2tf(f)); }

__device__ __forceinline__ void mma_tf32(float (&d)[4], const uint32_t (&a)[4],
                                         const uint32_t (&b)[2]) {
    asm volatile(
        "mma.sync.aligned.m16n8k8.row.col.f32.tf32.tf32.f32 "
        "{%0,%1,%2,%3}, {%4,%5,%6,%7}, {%8,%9}, {%0,%1,%2,%3};\n"
        : "+f"(d[0]), "+f"(d[1]), "+f"(d[2]), "+f"(d[3])
        : "r"(a[0]), "r"(a[1]), "r"(a[2]), "r"(a[3]), "r"(b[0]), "r"(b[1]));
}

__device__ __forceinline__ void cp16(const void* dst_smem, const void* src) {
    uint32_t d = (uint32_t)__cvta_generic_to_shared(dst_smem);
    asm volatile("cp.async.cg.shared.global [%0], [%1], 16;" :: "r"(d), "l"(src));
}
#define CP_COMMIT() asm volatile("cp.async.commit_group;" ::: "memory")
#define CP_WAIT0()  asm volatile("cp.async.wait_group 0;" ::: "memory")

// ---------------------------------------------------------------------------
// Kernel 1: projections (round-5 register-pipelined version; epilogue now
// writes tf32-rounded bit patterns so consumers can copy bytes directly).
// ---------------------------------------------------------------------------
__global__ __launch_bounds__(256, 2)
void proj_kernel(const float* __restrict__ Xq, const float* __restrict__ Xk,
                 const float* __restrict__ Xv, const float* __restrict__ Wq,
                 const float* __restrict__ Wk, const float* __restrict__ Wv,
                 float inv_scale)
{
    const float* A; const float* W; float* C; float alpha;
    int z = blockIdx.z;
    if (z == 0)      { A = Xq; W = Wq; C = g_Q; alpha = inv_scale; }
    else if (z == 1) { A = Xk; W = Wk; C = g_K; alpha = inv_scale; }
    else             { A = Xv; W = Wv; C = g_V; alpha = 1.0f; }

    const int K = 512, N = 512;

    __shared__ uint32_t As[2][BK][BM + 4];
    __shared__ uint32_t Bs[2][BK][BN + 4];

    int tid = threadIdx.x;
    int wid = tid >> 5, lane = tid & 31;
    int gid = lane >> 2, tig = lane & 3;
    int wm = wid >> 2, wn = wid & 3;
    int m0 = blockIdx.y * BM, n0 = blockIdx.x * BN;

    int arow = tid >> 2;
    int acol = (tid & 3) << 2;
    int brow = tid >> 5;
    int bcol = (tid & 31) << 2;

    float acc[4][4][4];
#pragma unroll
    for (int i = 0; i < 4; i++)
#pragma unroll
        for (int j = 0; j < 4; j++)
#pragma unroll
            for (int r = 0; r < 4; r++) acc[i][j][r] = 0.f;

    float4 ra[2], rb[2];
#define PROJ_LDG(k0)                                                          \
    do {                                                                      \
        ra[0] = *(const float4*)&A[(size_t)(m0 + arow) * K + (k0) + acol];    \
        ra[1] = *(const float4*)&A[(size_t)(m0 + arow + 64) * K + (k0) + acol]; \
        rb[0] = *(const float4*)&W[(size_t)((k0) + brow) * N + n0 + bcol];    \
        rb[1] = *(const float4*)&W[(size_t)((k0) + brow + 8) * N + n0 + bcol]; \
    } while (0)
#define PROJ_STS(buf)                                                         \
    do {                                                                      \
        _Pragma("unroll")                                                     \
        for (int p = 0; p < 2; p++) {                                         \
            As[buf][acol + 0][arow + p * 64] = f2tf(ra[p].x);                 \
            As[buf][acol + 1][arow + p * 64] = f2tf(ra[p].y);                 \
            As[buf][acol + 2][arow + p * 64] = f2tf(ra[p].z);                 \
            As[buf][acol + 3][arow + p * 64] = f2tf(ra[p].w);                 \
            uint4 u = make_uint4(f2tf(rb[p].x), f2tf(rb[p].y),                \
                                 f2tf(rb[p].z), f2tf(rb[p].w));               \
            *(uint4*)&Bs[buf][brow + p * 8][bcol] = u;                        \
        }                                                                     \
    } while (0)

    PROJ_LDG(0);
    PROJ_STS(0);
    __syncthreads();

    const int iters = K / BK;
    for (int it = 0; it < iters; it++) {
        int cur = it & 1;
        bool more = (it + 1 < iters);
        if (more) PROJ_LDG((it + 1) * BK);
#pragma unroll
        for (int ks = 0; ks < 2; ks++) {
            int kk = ks * 8;
            uint32_t af[4][4], bf[4][2];
#pragma unroll
            for (int mi = 0; mi < 4; mi++) {
                int m = wm * 64 + mi * 16 + gid;
                af[mi][0] = As[cur][kk + tig][m];
                af[mi][1] = As[cur][kk + tig][m + 8];
                af[mi][2] = As[cur][kk + tig + 4][m];
                af[mi][3] = As[cur][kk + tig + 4][m + 8];
            }
#pragma unroll
            for (int ni = 0; ni < 4; ni++) {
                int n = wn * 32 + ni * 8 + gid;
                bf[ni][0] = Bs[cur][kk + tig][n];
                bf[ni][1] = Bs[cur][kk + tig + 4][n];
            }
#pragma unroll
            for (int mi = 0; mi < 4; mi++)
#pragma unroll
                for (int ni = 0; ni < 4; ni++)
                    mma_tf32(acc[mi][ni], af[mi], bf[ni]);
        }
        if (more) PROJ_STS(cur ^ 1);
        __syncthreads();
    }
#undef PROJ_LDG
#undef PROJ_STS

#pragma unroll
    for (int mi = 0; mi < 4; mi++) {
        int r = m0 + wm * 64 + mi * 16 + gid;
#pragma unroll
        for (int ni = 0; ni < 4; ni++) {
            int c = n0 + wn * 32 + ni * 8 + tig * 2;
            *(float2*)&C[(size_t)r * N + c] =
                make_float2(f2tf_f(acc[mi][ni][0] * alpha), f2tf_f(acc[mi][ni][1] * alpha));
            *(float2*)&C[(size_t)(r + 8) * N + c] =
                make_float2(f2tf_f(acc[mi][ni][2] * alpha), f2tf_f(acc[mi][ni][3] * alpha));
        }
    }
}

// ---------------------------------------------------------------------------
// Kernel 2: masked scores. logits = Q Kt, NEGINF where mask==0. Per batch.
// Operands pre-rounded to tf32; cp.async staging into [row][20] layouts.
// ---------------------------------------------------------------------------
__global__ __launch_bounds__(256, 2)
void scores_kernel(const int* __restrict__ mask, float* __restrict__ out_p)
{
    int b = blockIdx.z;
    const float* Qb = g_Q + (size_t)b * SEQ * EMB;
    const float* Kb = g_K + (size_t)b * SEQ * EMB;
    const int*  Mb  = mask + (size_t)b * SEQ * SEQ;
    float*      Cb  = out_p + (size_t)b * SEQ * SEQ;

    __shared__ __align__(16) uint32_t As[2][128][20];
    __shared__ __align__(16) uint32_t Ks[2][128][20];

    int tid = threadIdx.x;
    int wid = tid >> 5, lane = tid & 31;
    int gid = lane >> 2, tig = lane & 3;
    int wm = wid >> 2, wn = wid & 3;
    int m0 = blockIdx.y * BM, n0 = blockIdx.x * BN;

    int srow = tid >> 2;            // 0..63
    int sseg = (tid & 3) << 2;      // 0,4,8,12

    float acc[4][4][4];
#pragma unroll
    for (int i = 0; i < 4; i++)
#pragma unroll
        for (int j = 0; j < 4; j++)
#pragma unroll
            for (int r = 0; r < 4; r++) acc[i][j][r] = 0.f;

#define SC_STAGE(buf, k0)                                                     \
    do {                                                                      \
        cp16(&As[buf][srow][sseg],      &Qb[(size_t)(m0 + srow) * EMB + (k0) + sseg]); \
        cp16(&As[buf][srow + 64][sseg], &Qb[(size_t)(m0 + srow + 64) * EMB + (k0) + sseg]); \
        cp16(&Ks[buf][srow][sseg],      &Kb[(size_t)(n0 + srow) * EMB + (k0) + sseg]); \
        cp16(&Ks[buf][srow + 64][sseg], &Kb[(size_t)(n0 + srow + 64) * EMB + (k0) + sseg]); \
        CP_COMMIT();                                                          \
    } while (0)

    SC_STAGE(0, 0);

    const int iters = EMB / BK;
    for (int it = 0; it < iters; it++) {
        int cur = it & 1;
        CP_WAIT0();
        __syncthreads();
        if (it + 1 < iters) SC_STAGE(cur ^ 1, (it + 1) * BK);
#pragma unroll
        for (int ks = 0; ks < 2; ks++) {
            int kk = ks * 8;
            uint32_t af[4][4], bf[4][2];
#pragma unroll
            for (int mi = 0; mi < 4; mi++) {
                int m = wm * 64 + mi * 16 + gid;
                af[mi][0] = As[cur][m][kk + tig];
                af[mi][1] = As[cur][m + 8][kk + tig];
                af[mi][2] = As[cur][m][kk + tig + 4];
                af[mi][3] = As[cur][m + 8][kk + tig + 4];
            }
#pragma unroll
            for (int ni = 0; ni < 4; ni++) {
                int n = wn * 32 + ni * 8 + gid;
                bf[ni][0] = Ks[cur][n][kk + tig];
                bf[ni][1] = Ks[cur][n][kk + tig + 4];
            }
#pragma unroll
            for (int mi = 0; mi < 4; mi++)
#pragma unroll
                for (int ni = 0; ni < 4; ni++)
                    mma_tf32(acc[mi][ni], af[mi], bf[ni]);
        }
    }
#undef SC_STAGE

#pragma unroll
    for (int mi = 0; mi < 4; mi++) {
        int r = m0 + wm * 64 + mi * 16 + gid;
#pragma unroll
        for (int ni = 0; ni < 4; ni++) {
            int c = n0 + wn * 32 + ni * 8 + tig * 2;
            size_t o0 = (size_t)r * SEQ + c;
            size_t o1 = (size_t)(r + 8) * SEQ + c;
            int2 mv0 = *(const int2*)&Mb[o0];
            int2 mv1 = *(const int2*)&Mb[o1];
            *(float2*)&Cb[o0] = make_float2(mv0.x ? acc[mi][ni][0] : NEGINF,
                                            mv0.y ? acc[mi][ni][1] : NEGINF);
            *(float2*)&Cb[o1] = make_float2(mv1.x ? acc[mi][ni][2] : NEGINF,
                                            mv1.y ? acc[mi][ni][3] : NEGINF);
        }
    }
}

// ---------------------------------------------------------------------------
// Kernel 3: row softmax (in place). Masked = NEGINF -> exactly 0.
// Outputs tf32-rounded so pv can byte-copy.
// ---------------------------------------------------------------------------
__global__ __launch_bounds__(256)
void softmax_kernel(float* __restrict__ P)
{
    float* prow = P + (size_t)blockIdx.x * SEQ;
    int tid = threadIdx.x;
    int lane = tid & 31, warp = tid >> 5;
    __shared__ float red[8];

    float4 v0 = ((const float4*)prow)[tid];
    float4 v1 = ((const float4*)prow)[tid + 256];
    float x[8] = {v0.x, v0.y, v0.z, v0.w, v1.x, v1.y, v1.z, v1.w};

    float m = x[0];
#pragma unroll
    for (int i = 1; i < 8; i++) m = fmaxf(m, x[i]);
#pragma unroll
    for (int o = 16; o > 0; o >>= 1) m = fmaxf(m, __shfl_xor_sync(0xFFFFFFFFu, m, o));
    if (lane == 0) red[warp] = m;
    __syncthreads();
    m = red[0];
#pragma unroll
    for (int i = 1; i < 8; i++) m = fmaxf(m, red[i]);

    if (m == NEGINF) {  // fully masked row
        float4 zz = make_float4(0.f, 0.f, 0.f, 0.f);
        ((float4*)prow)[tid] = zz;
        ((float4*)prow)[tid + 256] = zz;
        return;
    }

    float e[8], s = 0.f;
#pragma unroll
    for (int i = 0; i < 8; i++) { e[i] = __expf(x[i] - m); s += e[i]; }
#pragma unroll
    for (int o = 16; o > 0; o >>= 1) s += __shfl_xor_sync(0xFFFFFFFFu, s, o);
    __syncthreads();
    if (lane == 0) red[warp] = s;
    __syncthreads();
    s = 0.f;
#pragma unroll
    for (int i = 0; i < 8; i++) s += red[i];
    float inv = 1.0f / s;

    ((float4*)prow)[tid] = make_float4(f2tf_f(e[0] * inv), f2tf_f(e[1] * inv),
                                       f2tf_f(e[2] * inv), f2tf_f(e[3] * inv));
    ((float4*)prow)[tid + 256] = make_float4(f2tf_f(e[4] * inv), f2tf_f(e[5] * inv),
                                             f2tf_f(e[6] * inv), f2tf_f(e[7] * inv));
}

// ---------------------------------------------------------------------------
// Kernel 4: z = P @ V per batch. M=2048, N=512, K=2048.
// A = P rows ([row][20] layout), B = V k-rows ([k][136] layout, stride 8 mod 32).
// ---------------------------------------------------------------------------
__global__ __launch_bounds__(256, 2)
void pv_kernel(const float* __restrict__ P, float* __restrict__ out_z)
{
    int b = blockIdx.z;
    const float* Ab = P + (size_t)b * SEQ * SEQ;
    const float* Vb = g_V + (size_t)b * SEQ * EMB;
    float*       Cb = out_z + (size_t)b * SEQ * EMB;

    __shared__ __align__(16) uint32_t As[2][128][20];
    __shared__ __align__(16) uint32_t Bs[2][16][136];

    int tid = threadIdx.x;
    int wid = tid >> 5, lane = tid & 31;
    int gid = lane >> 2, tig = lane & 3;
    int wm = wid >> 2, wn = wid & 3;
    int m0 = blockIdx.y * BM, n0 = blockIdx.x * BN;

    int srow = tid >> 2;            // 0..63
    int sseg = (tid & 3) << 2;
    int brow = tid >> 5;            // 0..7
    int bseg = (tid & 31) << 2;     // 0..124

    float acc[4][4][4];
#pragma unroll
    for (int i = 0; i < 4; i++)
#pragma unroll
        for (int j = 0; j < 4; j++)
#pragma unroll
            for (int r = 0; r < 4; r++) acc[i][j][r] = 0.f;

#define PV_STAGE(buf, k0)                                                     \
    do {                                                                      \
        cp16(&As[buf][srow][sseg],      &Ab[(size_t)(m0 + srow) * SEQ + (k0) + sseg]); \
        cp16(&As[buf][srow + 64][sseg], &Ab[(size_t)(m0 + srow + 64) * SEQ + (k0) + sseg]); \
        cp16(&Bs[buf][brow][bseg],      &Vb[(size_t)((k0) + brow) * EMB + n0 + bseg]); \
        cp16(&Bs[buf][brow + 8][bseg],  &Vb[(size_t)((k0) + brow + 8) * EMB + n0 + bseg]); \
        CP_COMMIT();                                                          \
    } while (0)

    PV_STAGE(0, 0);

    const int iters = SEQ / BK;
    for (int it = 0; it < iters; it++) {
        int cur = it & 1;
        CP_WAIT0();
        __syncthreads();
        if (it + 1 < iters) PV_STAGE(cur ^ 1, (it + 1) * BK);
#pragma unroll
        for (int ks = 0; ks < 2; ks++) {
            int kk = ks * 8;
            uint32_t af[4][4], bf[4][2];
#pragma unroll
            for (int mi = 0; mi < 4; mi++) {
                int m = wm * 64 + mi * 16 + gid;
                af[mi][0] = As[cur][m][kk + tig];
                af[mi][1] = As[cur][m + 8][kk + tig];
                af[mi][2] = As[cur][m][kk + tig + 4];
                af[mi][3] = As[cur][m + 8][kk + tig + 4];
            }
#pragma unroll
            for (int ni = 0; ni < 4; ni++) {
                int n = wn * 32 + ni * 8 + gid;
                bf[ni][0] = Bs[cur][kk + tig][n];
                bf[ni][1] = Bs[cur][kk + tig + 4][n];
            }
#pragma unroll
            for (int mi = 0; mi < 4; mi++)
#pragma unroll
                for (int ni = 0; ni < 4; ni++)
                    mma_tf32(acc[mi][ni], af[mi], bf[ni]);
        }
    }
#undef PV_STAGE

#pragma unroll
    for (int mi = 0; mi < 4; mi++) {
        int r = m0 + wm * 64 + mi * 16 + gid;
#pragma unroll
        for (int ni = 0; ni < 4; ni++) {
            int c = n0 + wn * 32 + ni * 8 + tig * 2;
            *(float2*)&Cb[(size_t)r * EMB + c] = make_float2(acc[mi][ni][0], acc[mi][ni][1]);
            *(float2*)&Cb[(size_t)(r + 8) * EMB + c] = make_float2(acc[mi][ni][2], acc[mi][ni][3]);
        }
    }
}

// ---------------------------------------------------------------------------
// Launch. Inputs: Xin_q, Xin_k, Xin_v, mask, Wq, Wk, Wv.
// Output: z [8,2048,512] then attn_p [8,2048,2048], fp32.
// ---------------------------------------------------------------------------
extern "C" void kernel_launch(void* const* d_in, const int* in_sizes, int n_in,
                              void* d_out, int out_size)
{
    const float* Xq = (const float*)d_in[0];
    const float* Xk = (const float*)d_in[1];
    const float* Xv = (const float*)d_in[2];
    const int*   mk = (const int*)d_in[3];
    const float* Wq = (const float*)d_in[4];
    const float* Wk = (const float*)d_in[5];
    const float* Wv = (const float*)d_in[6];

    float* out_z = (float*)d_out;
    float* out_p = out_z + (size_t)BATCH * SEQ * EMB;

    const float inv_scale = 0.21022410381342864f;  // 1/512^(1/4)

    proj_kernel<<<dim3(EMB / BN, BSZ / BM, 3), 256>>>(Xq, Xk, Xv, Wq, Wk, Wv, inv_scale);
    scores_kernel<<<dim3(SEQ / BN, SEQ / BM, BATCH), 256>>>(mk, out_p);
    softmax_kernel<<<BSZ, 256>>>(out_p);
    pv_kernel<<<dim3(EMB / BN, SEQ / BM, BATCH), 256>>>(out_p, out_z);
}

// round 9
// speedup vs baseline: 1.7340x; 1.0362x over previous
#include <cuda_runtime.h>
#include <math.h>
#include <stdint.h>

#define NEGINF -1000000.0f

// Problem constants
#define BATCH 8
#define SEQ   2048
#define EMB   512
#define BSZ   (BATCH * SEQ)

// Scratch (no allocs allowed). Values stored as tf32-rounded fp32 bit patterns.
__device__ float g_Q[(size_t)BSZ * EMB];
__device__ float g_K[(size_t)BSZ * EMB];
__device__ float g_V[(size_t)BSZ * EMB];

#define BM 128
#define BN 128
#define BK 16
#define STAGES 4

__device__ __forceinline__ uint32_t f2tf(float f) {
    uint32_t r;
    asm("cvt.rna.tf32.f32 %0, %1;" : "=r"(r) : "f"(f));
    return r;
}
__device__ __forceinline__ float f2tf_f(float f) { return __uint_as_float(f2tf(f)); }

__device__ __forceinline__ void mma_tf32(float (&d)[4], const uint32_t (&a)[4],
                                         const uint32_t (&b)[2]) {
    asm volatile(
        "mma.sync.aligned.m16n8k8.row.col.f32.tf32.tf32.f32 "
        "{%0,%1,%2,%3}, {%4,%5,%6,%7}, {%8,%9}, {%0,%1,%2,%3};\n"
        : "+f"(d[0]), "+f"(d[1]), "+f"(d[2]), "+f"(d[3])
        : "r"(a[0]), "r"(a[1]), "r"(a[2]), "r"(a[3]), "r"(b[0]), "r"(b[1]));
}

__device__ __forceinline__ void cp16(const void* dst_smem, const void* src) {
    uint32_t d = (uint32_t)__cvta_generic_to_shared(dst_smem);
    asm volatile("cp.async.cg.shared.global [%0], [%1], 16;" :: "r"(d), "l"(src));
}
#define CP_COMMIT() asm volatile("cp.async.commit_group;" ::: "memory")
#define CP_WAIT2()  asm volatile("cp.async.wait_group 2;" ::: "memory")

// ---------------------------------------------------------------------------
// Kernel 1: projections (register-pipelined; writes tf32-rounded bit patterns
// so the downstream GEMMs can byte-copy operands).
// ---------------------------------------------------------------------------
__global__ __launch_bounds__(256, 2)
void proj_kernel(const float* __restrict__ Xq, const float* __restrict__ Xk,
                 const float* __restrict__ Xv, const float* __restrict__ Wq,
                 const float* __restrict__ Wk, const float* __restrict__ Wv,
                 float inv_scale)
{
    const float* A; const float* W; float* C; float alpha;
    int z = blockIdx.z;
    if (z == 0)      { A = Xq; W = Wq; C = g_Q; alpha = inv_scale; }
    else if (z == 1) { A = Xk; W = Wk; C = g_K; alpha = inv_scale; }
    else             { A = Xv; W = Wv; C = g_V; alpha = 1.0f; }

    const int K = 512, N = 512;

    __shared__ uint32_t As[2][BK][BM + 4];
    __shared__ uint32_t Bs[2][BK][BN + 4];

    int tid = threadIdx.x;
    int wid = tid >> 5, lane = tid & 31;
    int gid = lane >> 2, tig = lane & 3;
    int wm = wid >> 2, wn = wid & 3;
    int m0 = blockIdx.y * BM, n0 = blockIdx.x * BN;

    int arow = tid >> 2;
    int acol = (tid & 3) << 2;
    int brow = tid >> 5;
    int bcol = (tid & 31) << 2;

    float acc[4][4][4];
#pragma unroll
    for (int i = 0; i < 4; i++)
#pragma unroll
        for (int j = 0; j < 4; j++)
#pragma unroll
            for (int r = 0; r < 4; r++) acc[i][j][r] = 0.f;

    float4 ra[2], rb[2];
#define PROJ_LDG(k0)                                                          \
    do {                                                                      \
        ra[0] = *(const float4*)&A[(size_t)(m0 + arow) * K + (k0) + acol];    \
        ra[1] = *(const float4*)&A[(size_t)(m0 + arow + 64) * K + (k0) + acol]; \
        rb[0] = *(const float4*)&W[(size_t)((k0) + brow) * N + n0 + bcol];    \
        rb[1] = *(const float4*)&W[(size_t)((k0) + brow + 8) * N + n0 + bcol]; \
    } while (0)
#define PROJ_STS(buf)                                                         \
    do {                                                                      \
        _Pragma("unroll")                                                     \
        for (int p = 0; p < 2; p++) {                                         \
            As[buf][acol + 0][arow + p * 64] = f2tf(ra[p].x);                 \
            As[buf][acol + 1][arow + p * 64] = f2tf(ra[p].y);                 \
            As[buf][acol + 2][arow + p * 64] = f2tf(ra[p].z);                 \
            As[buf][acol + 3][arow + p * 64] = f2tf(ra[p].w);                 \
            uint4 u = make_uint4(f2tf(rb[p].x), f2tf(rb[p].y),                \
                                 f2tf(rb[p].z), f2tf(rb[p].w));               \
            *(uint4*)&Bs[buf][brow + p * 8][bcol] = u;                        \
        }                                                                     \
    } while (0)

    PROJ_LDG(0);
    PROJ_STS(0);
    __syncthreads();

    const int iters = K / BK;
    for (int it = 0; it < iters; it++) {
        int cur = it & 1;
        bool more = (it + 1 < iters);
        if (more) PROJ_LDG((it + 1) * BK);
#pragma unroll
        for (int ks = 0; ks < 2; ks++) {
            int kk = ks * 8;
            uint32_t af[4][4], bf[4][2];
#pragma unroll
            for (int mi = 0; mi < 4; mi++) {
                int m = wm * 64 + mi * 16 + gid;
                af[mi][0] = As[cur][kk + tig][m];
                af[mi][1] = As[cur][kk + tig][m + 8];
                af[mi][2] = As[cur][kk + tig + 4][m];
                af[mi][3] = As[cur][kk + tig + 4][m + 8];
            }
#pragma unroll
            for (int ni = 0; ni < 4; ni++) {
                int n = wn * 32 + ni * 8 + gid;
                bf[ni][0] = Bs[cur][kk + tig][n];
                bf[ni][1] = Bs[cur][kk + tig + 4][n];
            }
#pragma unroll
            for (int mi = 0; mi < 4; mi++)
#pragma unroll
                for (int ni = 0; ni < 4; ni++)
                    mma_tf32(acc[mi][ni], af[mi], bf[ni]);
        }
        if (more) PROJ_STS(cur ^ 1);
        __syncthreads();
    }
#undef PROJ_LDG
#undef PROJ_STS

#pragma unroll
    for (int mi = 0; mi < 4; mi++) {
        int r = m0 + wm * 64 + mi * 16 + gid;
#pragma unroll
        for (int ni = 0; ni < 4; ni++) {
            int c = n0 + wn * 32 + ni * 8 + tig * 2;
            *(float2*)&C[(size_t)r * N + c] =
                make_float2(f2tf_f(acc[mi][ni][0] * alpha), f2tf_f(acc[mi][ni][1] * alpha));
            *(float2*)&C[(size_t)(r + 8) * N + c] =
                make_float2(f2tf_f(acc[mi][ni][2] * alpha), f2tf_f(acc[mi][ni][3] * alpha));
        }
    }
}

// ---------------------------------------------------------------------------
// Kernel 2: masked scores. 4-stage cp.async ring, prefetch distance 3.
// Dynamic smem: As[4][128][20] + Ks[4][128][20] = 81920 B.
// ---------------------------------------------------------------------------
__global__ __launch_bounds__(256, 2)
void scores_kernel(const int* __restrict__ mask, float* __restrict__ out_p)
{
    extern __shared__ uint32_t dsm[];
    uint32_t (*As)[128][20] = (uint32_t (*)[128][20])dsm;
    uint32_t (*Ks)[128][20] = (uint32_t (*)[128][20])(dsm + STAGES * 128 * 20);

    int b = blockIdx.z;
    const float* Qb = g_Q + (size_t)b * SEQ * EMB;
    const float* Kb = g_K + (size_t)b * SEQ * EMB;
    const int*  Mb  = mask + (size_t)b * SEQ * SEQ;
    float*      Cb  = out_p + (size_t)b * SEQ * SEQ;

    int tid = threadIdx.x;
    int wid = tid >> 5, lane = tid & 31;
    int gid = lane >> 2, tig = lane & 3;
    int wm = wid >> 2, wn = wid & 3;
    int m0 = blockIdx.y * BM, n0 = blockIdx.x * BN;

    int srow = tid >> 2;            // 0..63
    int sseg = (tid & 3) << 2;      // 0,4,8,12

    float acc[4][4][4];
#pragma unroll
    for (int i = 0; i < 4; i++)
#pragma unroll
        for (int j = 0; j < 4; j++)
#pragma unroll
            for (int r = 0; r < 4; r++) acc[i][j][r] = 0.f;

#define SC_STAGE(buf, k0)                                                     \
    do {                                                                      \
        cp16(&As[buf][srow][sseg],      &Qb[(size_t)(m0 + srow) * EMB + (k0) + sseg]); \
        cp16(&As[buf][srow + 64][sseg], &Qb[(size_t)(m0 + srow + 64) * EMB + (k0) + sseg]); \
        cp16(&Ks[buf][srow][sseg],      &Kb[(size_t)(n0 + srow) * EMB + (k0) + sseg]); \
        cp16(&Ks[buf][srow + 64][sseg], &Kb[(size_t)(n0 + srow + 64) * EMB + (k0) + sseg]); \
        CP_COMMIT();                                                          \
    } while (0)

    const int iters = EMB / BK;   // 32
    SC_STAGE(0, 0);
    SC_STAGE(1, BK);
    SC_STAGE(2, 2 * BK);

    for (int it = 0; it < iters; it++) {
        int cur = it & 3;
        CP_WAIT2();
        __syncthreads();
        if (it + 3 < iters) SC_STAGE((it + 3) & 3, (it + 3) * BK);
        else CP_COMMIT();
#pragma unroll
        for (int ks = 0; ks < 2; ks++) {
            int kk = ks * 8;
            uint32_t af[4][4], bf[4][2];
#pragma unroll
            for (int mi = 0; mi < 4; mi++) {
                int m = wm * 64 + mi * 16 + gid;
                af[mi][0] = As[cur][m][kk + tig];
                af[mi][1] = As[cur][m + 8][kk + tig];
                af[mi][2] = As[cur][m][kk + tig + 4];
                af[mi][3] = As[cur][m + 8][kk + tig + 4];
            }
#pragma unroll
            for (int ni = 0; ni < 4; ni++) {
                int n = wn * 32 + ni * 8 + gid;
                bf[ni][0] = Ks[cur][n][kk + tig];
                bf[ni][1] = Ks[cur][n][kk + tig + 4];
            }
#pragma unroll
            for (int mi = 0; mi < 4; mi++)
#pragma unroll
                for (int ni = 0; ni < 4; ni++)
                    mma_tf32(acc[mi][ni], af[mi], bf[ni]);
        }
    }
#undef SC_STAGE

#pragma unroll
    for (int mi = 0; mi < 4; mi++) {
        int r = m0 + wm * 64 + mi * 16 + gid;
#pragma unroll
        for (int ni = 0; ni < 4; ni++) {
            int c = n0 + wn * 32 + ni * 8 + tig * 2;
            size_t o0 = (size_t)r * SEQ + c;
            size_t o1 = (size_t)(r + 8) * SEQ + c;
            int2 mv0 = *(const int2*)&Mb[o0];
            int2 mv1 = *(const int2*)&Mb[o1];
            *(float2*)&Cb[o0] = make_float2(mv0.x ? acc[mi][ni][0] : NEGINF,
                                            mv0.y ? acc[mi][ni][1] : NEGINF);
            *(float2*)&Cb[o1] = make_float2(mv1.x ? acc[mi][ni][2] : NEGINF,
                                            mv1.y ? acc[mi][ni][3] : NEGINF);
        }
    }
}

// ---------------------------------------------------------------------------
// Kernel 3: row softmax (in place). Masked = NEGINF -> exactly 0.
// Outputs tf32-rounded so pv can byte-copy.
// ---------------------------------------------------------------------------
__global__ __launch_bounds__(256)
void softmax_kernel(float* __restrict__ P)
{
    float* prow = P + (size_t)blockIdx.x * SEQ;
    int tid = threadIdx.x;
    int lane = tid & 31, warp = tid >> 5;
    __shared__ float red[8];

    float4 v0 = ((const float4*)prow)[tid];
    float4 v1 = ((const float4*)prow)[tid + 256];
    float x[8] = {v0.x, v0.y, v0.z, v0.w, v1.x, v1.y, v1.z, v1.w};

    float m = x[0];
#pragma unroll
    for (int i = 1; i < 8; i++) m = fmaxf(m, x[i]);
#pragma unroll
    for (int o = 16; o > 0; o >>= 1) m = fmaxf(m, __shfl_xor_sync(0xFFFFFFFFu, m, o));
    if (lane == 0) red[warp] = m;
    __syncthreads();
    m = red[0];
#pragma unroll
    for (int i = 1; i < 8; i++) m = fmaxf(m, red[i]);

    if (m == NEGINF) {  // fully masked row
        float4 zz = make_float4(0.f, 0.f, 0.f, 0.f);
        ((float4*)prow)[tid] = zz;
        ((float4*)prow)[tid + 256] = zz;
        return;
    }

    float e[8], s = 0.f;
#pragma unroll
    for (int i = 0; i < 8; i++) { e[i] = __expf(x[i] - m); s += e[i]; }
#pragma unroll
    for (int o = 16; o > 0; o >>= 1) s += __shfl_xor_sync(0xFFFFFFFFu, s, o);
    __syncthreads();
    if (lane == 0) red[warp] = s;
    __syncthreads();
    s = 0.f;
#pragma unroll
    for (int i = 0; i < 8; i++) s += red[i];
    float inv = 1.0f / s;

    ((float4*)prow)[tid] = make_float4(f2tf_f(e[0] * inv), f2tf_f(e[1] * inv),
                                       f2tf_f(e[2] * inv), f2tf_f(e[3] * inv));
    ((float4*)prow)[tid + 256] = make_float4(f2tf_f(e[4] * inv), f2tf_f(e[5] * inv),
                                             f2tf_f(e[6] * inv), f2tf_f(e[7] * inv));
}

// ---------------------------------------------------------------------------
// Kernel 4: z = P @ V per batch. 4-stage cp.async ring, prefetch distance 3.
// Dynamic smem: As[4][128][20] + Bs[4][16][136] = 75776 B.
// ---------------------------------------------------------------------------
__global__ __launch_bounds__(256, 2)
void pv_kernel(const float* __restrict__ P, float* __restrict__ out_z)
{
    extern __shared__ uint32_t dsm[];
    uint32_t (*As)[128][20] = (uint32_t (*)[128][20])dsm;
    uint32_t (*Bs)[16][136] = (uint32_t (*)[16][136])(dsm + STAGES * 128 * 20);

    int b = blockIdx.z;
    const float* Ab = P + (size_t)b * SEQ * SEQ;
    const float* Vb = g_V + (size_t)b * SEQ * EMB;
    float*       Cb = out_z + (size_t)b * SEQ * EMB;

    int tid = threadIdx.x;
    int wid = tid >> 5, lane = tid & 31;
    int gid = lane >> 2, tig = lane & 3;
    int wm = wid >> 2, wn = wid & 3;
    int m0 = blockIdx.y * BM, n0 = blockIdx.x * BN;

    int srow = tid >> 2;            // 0..63
    int sseg = (tid & 3) << 2;
    int brow = tid >> 5;            // 0..7
    int bseg = (tid & 31) << 2;     // 0..124

    float acc[4][4][4];
#pragma unroll
    for (int i = 0; i < 4; i++)
#pragma unroll
        for (int j = 0; j < 4; j++)
#pragma unroll
            for (int r = 0; r < 4; r++) acc[i][j][r] = 0.f;

#define PV_STAGE(buf, k0)                                                     \
    do {                                                                      \
        cp16(&As[buf][srow][sseg],      &Ab[(size_t)(m0 + srow) * SEQ + (k0) + sseg]); \
        cp16(&As[buf][srow + 64][sseg], &Ab[(size_t)(m0 + srow + 64) * SEQ + (k0) + sseg]); \
        cp16(&Bs[buf][brow][bseg],      &Vb[(size_t)((k0) + brow) * EMB + n0 + bseg]); \
        cp16(&Bs[buf][brow + 8][bseg],  &Vb[(size_t)((k0) + brow + 8) * EMB + n0 + bseg]); \
        CP_COMMIT();                                                          \
    } while (0)

    const int iters = SEQ / BK;   // 128
    PV_STAGE(0, 0);
    PV_STAGE(1, BK);
    PV_STAGE(2, 2 * BK);

    for (int it = 0; it < iters; it++) {
        int cur = it & 3;
        CP_WAIT2();
        __syncthreads();
        if (it + 3 < iters) PV_STAGE((it + 3) & 3, (it + 3) * BK);
        else CP_COMMIT();
#pragma unroll
        for (int ks = 0; ks < 2; ks++) {
            int kk = ks * 8;
            uint32_t af[4][4], bf[4][2];
#pragma unroll
            for (int mi = 0; mi < 4; mi++) {
                int m = wm * 64 + mi * 16 + gid;
                af[mi][0] = As[cur][m][kk + tig];
                af[mi][1] = As[cur][m + 8][kk + tig];
                af[mi][2] = As[cur][m][kk + tig + 4];
                af[mi][3] = As[cur][m + 8][kk + tig + 4];
            }
#pragma unroll
            for (int ni = 0; ni < 4; ni++) {
                int n = wn * 32 + ni * 8 + gid;
                bf[ni][0] = Bs[cur][kk + tig][n];
                bf[ni][1] = Bs[cur][kk + tig + 4][n];
            }
#pragma unroll
            for (int mi = 0; mi < 4; mi++)
#pragma unroll
                for (int ni = 0; ni < 4; ni++)
                    mma_tf32(acc[mi][ni], af[mi], bf[ni]);
        }
    }
#undef PV_STAGE

#pragma unroll
    for (int mi = 0; mi < 4; mi++) {
        int r = m0 + wm * 64 + mi * 16 + gid;
#pragma unroll
        for (int ni = 0; ni < 4; ni++) {
            int c = n0 + wn * 32 + ni * 8 + tig * 2;
            *(float2*)&Cb[(size_t)r * EMB + c] = make_float2(acc[mi][ni][0], acc[mi][ni][1]);
            *(float2*)&Cb[(size_t)(r + 8) * EMB + c] = make_float2(acc[mi][ni][2], acc[mi][ni][3]);
        }
    }
}

// ---------------------------------------------------------------------------
// Launch. Inputs: Xin_q, Xin_k, Xin_v, mask, Wq, Wk, Wv.
// Output: z [8,2048,512] then attn_p [8,2048,2048], fp32.
// ---------------------------------------------------------------------------
extern "C" void kernel_launch(void* const* d_in, const int* in_sizes, int n_in,
                              void* d_out, int out_size)
{
    const float* Xq = (const float*)d_in[0];
    const float* Xk = (const float*)d_in[1];
    const float* Xv = (const float*)d_in[2];
    const int*   mk = (const int*)d_in[3];
    const float* Wq = (const float*)d_in[4];
    const float* Wk = (const float*)d_in[5];
    const float* Wv = (const float*)d_in[6];

    float* out_z = (float*)d_out;
    float* out_p = out_z + (size_t)BATCH * SEQ * EMB;

    const float inv_scale = 0.21022410381342864f;  // 1/512^(1/4)

    const int SC_SMEM = STAGES * (128 * 20 + 128 * 20) * 4;   // 81920 B
    const int PV_SMEM = STAGES * (128 * 20 + 16 * 136) * 4;   // 75776 B
    cudaFuncSetAttribute(scores_kernel, cudaFuncAttributeMaxDynamicSharedMemorySize, SC_SMEM);
    cudaFuncSetAttribute(pv_kernel, cudaFuncAttributeMaxDynamicSharedMemorySize, PV_SMEM);

    proj_kernel<<<dim3(EMB / BN, BSZ / BM, 3), 256>>>(Xq, Xk, Xv, Wq, Wk, Wv, inv_scale);
    scores_kernel<<<dim3(SEQ / BN, SEQ / BM, BATCH), 256, SC_SMEM>>>(mk, out_p);
    softmax_kernel<<<BSZ, 256>>>(out_p);
    pv_kernel<<<dim3(EMB / BN, SEQ / BM, BATCH), 256, PV_SMEM>>>(out_p, out_z);
}

// round 10
// speedup vs baseline: 1.8375x; 1.0597x over previous
#include <cuda_runtime.h>
#include <math.h>
#include <stdint.h>

#define NEGINF -1000000.0f

// Problem constants
#define BATCH 8
#define SEQ   2048
#define EMB   512
#define BSZ   (BATCH * SEQ)

// Scratch (no allocs allowed). Values stored as tf32-rounded fp32 bit patterns.
__device__ float g_Q[(size_t)BSZ * EMB];
__device__ float g_K[(size_t)BSZ * EMB];
__device__ float g_V[(size_t)BSZ * EMB];

#define BM 128
#define BN 128
#define BK 32          // scores/pv chunk
#define STAGES 3       // ring depth, prefetch distance 2

__device__ __forceinline__ uint32_t f2tf(float f) {
    uint32_t r;
    asm("cvt.rna.tf32.f32 %0, %1;" : "=r"(r) : "f"(f));
    return r;
}
__device__ __forceinline__ float f2tf_f(float f) { return __uint_as_float(f2tf(f)); }

__device__ __forceinline__ void mma_tf32(float (&d)[4], const uint32_t (&a)[4],
                                         const uint32_t (&b)[2]) {
    asm volatile(
        "mma.sync.aligned.m16n8k8.row.col.f32.tf32.tf32.f32 "
        "{%0,%1,%2,%3}, {%4,%5,%6,%7}, {%8,%9}, {%0,%1,%2,%3};\n"
        : "+f"(d[0]), "+f"(d[1]), "+f"(d[2]), "+f"(d[3])
        : "r"(a[0]), "r"(a[1]), "r"(a[2]), "r"(a[3]), "r"(b[0]), "r"(b[1]));
}

__device__ __forceinline__ void cp16(const void* dst_smem, const void* src) {
    uint32_t d = (uint32_t)__cvta_generic_to_shared(dst_smem);
    asm volatile("cp.async.cg.shared.global [%0], [%1], 16;" :: "r"(d), "l"(src));
}
#define CP_COMMIT() asm volatile("cp.async.commit_group;" ::: "memory")
#define CP_WAIT1()  asm volatile("cp.async.wait_group 1;" ::: "memory")

// ---------------------------------------------------------------------------
// Kernel 1: projections (register-pipelined BK=16; writes tf32-rounded bit
// patterns so the downstream GEMMs can byte-copy operands). Unchanged.
// ---------------------------------------------------------------------------
__global__ __launch_bounds__(256, 2)
void proj_kernel(const float* __restrict__ Xq, const float* __restrict__ Xk,
                 const float* __restrict__ Xv, const float* __restrict__ Wq,
                 const float* __restrict__ Wk, const float* __restrict__ Wv,
                 float inv_scale)
{
    const float* A; const float* W; float* C; float alpha;
    int z = blockIdx.z;
    if (z == 0)      { A = Xq; W = Wq; C = g_Q; alpha = inv_scale; }
    else if (z == 1) { A = Xk; W = Wk; C = g_K; alpha = inv_scale; }
    else             { A = Xv; W = Wv; C = g_V; alpha = 1.0f; }

    const int K = 512, N = 512;
    const int PBK = 16;

    __shared__ uint32_t As[2][PBK][BM + 4];
    __shared__ uint32_t Bs[2][PBK][BN + 4];

    int tid = threadIdx.x;
    int wid = tid >> 5, lane = tid & 31;
    int gid = lane >> 2, tig = lane & 3;
    int wm = wid >> 2, wn = wid & 3;
    int m0 = blockIdx.y * BM, n0 = blockIdx.x * BN;

    int arow = tid >> 2;
    int acol = (tid & 3) << 2;
    int brow = tid >> 5;
    int bcol = (tid & 31) << 2;

    float acc[4][4][4];
#pragma unroll
    for (int i = 0; i < 4; i++)
#pragma unroll
        for (int j = 0; j < 4; j++)
#pragma unroll
            for (int r = 0; r < 4; r++) acc[i][j][r] = 0.f;

    float4 ra[2], rb[2];
#define PROJ_LDG(k0)                                                          \
    do {                                                                      \
        ra[0] = *(const float4*)&A[(size_t)(m0 + arow) * K + (k0) + acol];    \
        ra[1] = *(const float4*)&A[(size_t)(m0 + arow + 64) * K + (k0) + acol]; \
        rb[0] = *(const float4*)&W[(size_t)((k0) + brow) * N + n0 + bcol];    \
        rb[1] = *(const float4*)&W[(size_t)((k0) + brow + 8) * N + n0 + bcol]; \
    } while (0)
#define PROJ_STS(buf)                                                         \
    do {                                                                      \
        _Pragma("unroll")                                                     \
        for (int p = 0; p < 2; p++) {                                         \
            As[buf][acol + 0][arow + p * 64] = f2tf(ra[p].x);                 \
            As[buf][acol + 1][arow + p * 64] = f2tf(ra[p].y);                 \
            As[buf][acol + 2][arow + p * 64] = f2tf(ra[p].z);                 \
            As[buf][acol + 3][arow + p * 64] = f2tf(ra[p].w);                 \
            uint4 u = make_uint4(f2tf(rb[p].x), f2tf(rb[p].y),                \
                                 f2tf(rb[p].z), f2tf(rb[p].w));               \
            *(uint4*)&Bs[buf][brow + p * 8][bcol] = u;                        \
        }                                                                     \
    } while (0)

    PROJ_LDG(0);
    PROJ_STS(0);
    __syncthreads();

    const int iters = K / PBK;
    for (int it = 0; it < iters; it++) {
        int cur = it & 1;
        bool more = (it + 1 < iters);
        if (more) PROJ_LDG((it + 1) * PBK);
#pragma unroll
        for (int ks = 0; ks < 2; ks++) {
            int kk = ks * 8;
            uint32_t af[4][4], bf[4][2];
#pragma unroll
            for (int mi = 0; mi < 4; mi++) {
                int m = wm * 64 + mi * 16 + gid;
                af[mi][0] = As[cur][kk + tig][m];
                af[mi][1] = As[cur][kk + tig][m + 8];
                af[mi][2] = As[cur][kk + tig + 4][m];
                af[mi][3] = As[cur][kk + tig + 4][m + 8];
            }
#pragma unroll
            for (int ni = 0; ni < 4; ni++) {
                int n = wn * 32 + ni * 8 + gid;
                bf[ni][0] = Bs[cur][kk + tig][n];
                bf[ni][1] = Bs[cur][kk + tig + 4][n];
            }
#pragma unroll
            for (int mi = 0; mi < 4; mi++)
#pragma unroll
                for (int ni = 0; ni < 4; ni++)
                    mma_tf32(acc[mi][ni], af[mi], bf[ni]);
        }
        if (more) PROJ_STS(cur ^ 1);
        __syncthreads();
    }
#undef PROJ_LDG
#undef PROJ_STS

#pragma unroll
    for (int mi = 0; mi < 4; mi++) {
        int r = m0 + wm * 64 + mi * 16 + gid;
#pragma unroll
        for (int ni = 0; ni < 4; ni++) {
            int c = n0 + wn * 32 + ni * 8 + tig * 2;
            *(float2*)&C[(size_t)r * N + c] =
                make_float2(f2tf_f(acc[mi][ni][0] * alpha), f2tf_f(acc[mi][ni][1] * alpha));
            *(float2*)&C[(size_t)(r + 8) * N + c] =
                make_float2(f2tf_f(acc[mi][ni][2] * alpha), f2tf_f(acc[mi][ni][3] * alpha));
        }
    }
}

// ---------------------------------------------------------------------------
// Kernel 2: masked scores. BK=32, 3-stage cp.async ring (distance 2).
// Dynamic smem: Qs[3][128][36] + Ks[3][128][36] = 110592 B.
// ---------------------------------------------------------------------------
__global__ __launch_bounds__(256, 2)
void scores_kernel(const int* __restrict__ mask, float* __restrict__ out_p)
{
    extern __shared__ uint32_t dsm[];
    uint32_t (*Qs)[128][36] = (uint32_t (*)[128][36])dsm;
    uint32_t (*Ks)[128][36] = (uint32_t (*)[128][36])(dsm + STAGES * 128 * 36);

    int b = blockIdx.z;
    const float* Qb = g_Q + (size_t)b * SEQ * EMB;
    const float* Kb = g_K + (size_t)b * SEQ * EMB;
    const int*  Mb  = mask + (size_t)b * SEQ * SEQ;
    float*      Cb  = out_p + (size_t)b * SEQ * SEQ;

    int tid = threadIdx.x;
    int wid = tid >> 5, lane = tid & 31;
    int gid = lane >> 2, tig = lane & 3;
    int wm = wid >> 2, wn = wid & 3;
    int m0 = blockIdx.y * BM, n0 = blockIdx.x * BN;

    int srow = tid >> 3;            // 0..31 (row within 32-row pass)
    int sseg = (tid & 7) << 2;      // 0..28 (k-segment)

    float acc[4][4][4];
#pragma unroll
    for (int i = 0; i < 4; i++)
#pragma unroll
        for (int j = 0; j < 4; j++)
#pragma unroll
            for (int r = 0; r < 4; r++) acc[i][j][r] = 0.f;

#define SC_STAGE(buf, k0)                                                     \
    do {                                                                      \
        _Pragma("unroll")                                                     \
        for (int p = 0; p < 4; p++) {                                         \
            cp16(&Qs[buf][p * 32 + srow][sseg],                               \
                 &Qb[(size_t)(m0 + p * 32 + srow) * EMB + (k0) + sseg]);      \
            cp16(&Ks[buf][p * 32 + srow][sseg],                               \
                 &Kb[(size_t)(n0 + p * 32 + srow) * EMB + (k0) + sseg]);      \
        }                                                                     \
        CP_COMMIT();                                                          \
    } while (0)

    const int iters = EMB / BK;   // 16
    SC_STAGE(0, 0);
    SC_STAGE(1, BK);

    int cur = 0, wr = 2;
    for (int it = 0; it < iters; it++) {
        CP_WAIT1();
        __syncthreads();
        if (it + 2 < iters) SC_STAGE(wr, (it + 2) * BK);
        else CP_COMMIT();
#pragma unroll
        for (int ks = 0; ks < 4; ks++) {
            int kk = ks * 8;
            uint32_t af[4][4], bf[4][2];
#pragma unroll
            for (int mi = 0; mi < 4; mi++) {
                int m = wm * 64 + mi * 16 + gid;
                af[mi][0] = Qs[cur][m][kk + tig];
                af[mi][1] = Qs[cur][m + 8][kk + tig];
                af[mi][2] = Qs[cur][m][kk + tig + 4];
                af[mi][3] = Qs[cur][m + 8][kk + tig + 4];
            }
#pragma unroll
            for (int ni = 0; ni < 4; ni++) {
                int n = wn * 32 + ni * 8 + gid;
                bf[ni][0] = Ks[cur][n][kk + tig];
                bf[ni][1] = Ks[cur][n][kk + tig + 4];
            }
#pragma unroll
            for (int mi = 0; mi < 4; mi++)
#pragma unroll
                for (int ni = 0; ni < 4; ni++)
                    mma_tf32(acc[mi][ni], af[mi], bf[ni]);
        }
        cur = (cur == STAGES - 1) ? 0 : cur + 1;
        wr  = (wr  == STAGES - 1) ? 0 : wr + 1;
    }
#undef SC_STAGE

#pragma unroll
    for (int mi = 0; mi < 4; mi++) {
        int r = m0 + wm * 64 + mi * 16 + gid;
#pragma unroll
        for (int ni = 0; ni < 4; ni++) {
            int c = n0 + wn * 32 + ni * 8 + tig * 2;
            size_t o0 = (size_t)r * SEQ + c;
            size_t o1 = (size_t)(r + 8) * SEQ + c;
            int2 mv0 = *(const int2*)&Mb[o0];
            int2 mv1 = *(const int2*)&Mb[o1];
            *(float2*)&Cb[o0] = make_float2(mv0.x ? acc[mi][ni][0] : NEGINF,
                                            mv0.y ? acc[mi][ni][1] : NEGINF);
            *(float2*)&Cb[o1] = make_float2(mv1.x ? acc[mi][ni][2] : NEGINF,
                                            mv1.y ? acc[mi][ni][3] : NEGINF);
        }
    }
}

// ---------------------------------------------------------------------------
// Kernel 3: row softmax (in place). Masked = NEGINF -> exactly 0.
// Outputs tf32-rounded so pv can byte-copy.
// ---------------------------------------------------------------------------
__global__ __launch_bounds__(256)
void softmax_kernel(float* __restrict__ P)
{
    float* prow = P + (size_t)blockIdx.x * SEQ;
    int tid = threadIdx.x;
    int lane = tid & 31, warp = tid >> 5;
    __shared__ float red[8];

    float4 v0 = ((const float4*)prow)[tid];
    float4 v1 = ((const float4*)prow)[tid + 256];
    float x[8] = {v0.x, v0.y, v0.z, v0.w, v1.x, v1.y, v1.z, v1.w};

    float m = x[0];
#pragma unroll
    for (int i = 1; i < 8; i++) m = fmaxf(m, x[i]);
#pragma unroll
    for (int o = 16; o > 0; o >>= 1) m = fmaxf(m, __shfl_xor_sync(0xFFFFFFFFu, m, o));
    if (lane == 0) red[warp] = m;
    __syncthreads();
    m = red[0];
#pragma unroll
    for (int i = 1; i < 8; i++) m = fmaxf(m, red[i]);

    if (m == NEGINF) {  // fully masked row
        float4 zz = make_float4(0.f, 0.f, 0.f, 0.f);
        ((float4*)prow)[tid] = zz;
        ((float4*)prow)[tid + 256] = zz;
        return;
    }

    float e[8], s = 0.f;
#pragma unroll
    for (int i = 0; i < 8; i++) { e[i] = __expf(x[i] - m); s += e[i]; }
#pragma unroll
    for (int o = 16; o > 0; o >>= 1) s += __shfl_xor_sync(0xFFFFFFFFu, s, o);
    __syncthreads();
    if (lane == 0) red[warp] = s;
    __syncthreads();
    s = 0.f;
#pragma unroll
    for (int i = 0; i < 8; i++) s += red[i];
    float inv = 1.0f / s;

    ((float4*)prow)[tid] = make_float4(f2tf_f(e[0] * inv), f2tf_f(e[1] * inv),
                                       f2tf_f(e[2] * inv), f2tf_f(e[3] * inv));
    ((float4*)prow)[tid + 256] = make_float4(f2tf_f(e[4] * inv), f2tf_f(e[5] * inv),
                                             f2tf_f(e[6] * inv), f2tf_f(e[7] * inv));
}

// ---------------------------------------------------------------------------
// Kernel 4: z = P @ V per batch. BK=32, 3-stage cp.async ring (distance 2).
// Dynamic smem: As[3][128][36] + Bs[3][32][136] = 107520 B.
// ---------------------------------------------------------------------------
__global__ __launch_bounds__(256, 2)
void pv_kernel(const float* __restrict__ P, float* __restrict__ out_z)
{
    extern __shared__ uint32_t dsm[];
    uint32_t (*As)[128][36] = (uint32_t (*)[128][36])dsm;
    uint32_t (*Bs)[32][136] = (uint32_t (*)[32][136])(dsm + STAGES * 128 * 36);

    int b = blockIdx.z;
    const float* Ab = P + (size_t)b * SEQ * SEQ;
    const float* Vb = g_V + (size_t)b * SEQ * EMB;
    float*       Cb = out_z + (size_t)b * SEQ * EMB;

    int tid = threadIdx.x;
    int wid = tid >> 5, lane = tid & 31;
    int gid = lane >> 2, tig = lane & 3;
    int wm = wid >> 2, wn = wid & 3;
    int m0 = blockIdx.y * BM, n0 = blockIdx.x * BN;

    int srow = tid >> 3;            // 0..31
    int sseg = (tid & 7) << 2;      // 0..28
    int brow = tid >> 5;            // 0..7
    int bseg = (tid & 31) << 2;     // 0..124

    float acc[4][4][4];
#pragma unroll
    for (int i = 0; i < 4; i++)
#pragma unroll
        for (int j = 0; j < 4; j++)
#pragma unroll
            for (int r = 0; r < 4; r++) acc[i][j][r] = 0.f;

#define PV_STAGE(buf, k0)                                                     \
    do {                                                                      \
        _Pragma("unroll")                                                     \
        for (int p = 0; p < 4; p++)                                           \
            cp16(&As[buf][p * 32 + srow][sseg],                               \
                 &Ab[(size_t)(m0 + p * 32 + srow) * SEQ + (k0) + sseg]);      \
        _Pragma("unroll")                                                     \
        for (int p = 0; p < 4; p++)                                           \
            cp16(&Bs[buf][p * 8 + brow][bseg],                                \
                 &Vb[(size_t)((k0) + p * 8 + brow) * EMB + n0 + bseg]);       \
        CP_COMMIT();                                                          \
    } while (0)

    const int iters = SEQ / BK;   // 64
    PV_STAGE(0, 0);
    PV_STAGE(1, BK);

    int cur = 0, wr = 2;
    for (int it = 0; it < iters; it++) {
        CP_WAIT1();
        __syncthreads();
        if (it + 2 < iters) PV_STAGE(wr, (it + 2) * BK);
        else CP_COMMIT();
#pragma unroll
        for (int ks = 0; ks < 4; ks++) {
            int kk = ks * 8;
            uint32_t af[4][4], bf[4][2];
#pragma unroll
            for (int mi = 0; mi < 4; mi++) {
                int m = wm * 64 + mi * 16 + gid;
                af[mi][0] = As[cur][m][kk + tig];
                af[mi][1] = As[cur][m + 8][kk + tig];
                af[mi][2] = As[cur][m][kk + tig + 4];
                af[mi][3] = As[cur][m + 8][kk + tig + 4];
            }
#pragma unroll
            for (int ni = 0; ni < 4; ni++) {
                int n = wn * 32 + ni * 8 + gid;
                bf[ni][0] = Bs[cur][kk + tig][n];
                bf[ni][1] = Bs[cur][kk + tig + 4][n];
            }
#pragma unroll
            for (int mi = 0; mi < 4; mi++)
#pragma unroll
                for (int ni = 0; ni < 4; ni++)
                    mma_tf32(acc[mi][ni], af[mi], bf[ni]);
        }
        cur = (cur == STAGES - 1) ? 0 : cur + 1;
        wr  = (wr  == STAGES - 1) ? 0 : wr + 1;
    }
#undef PV_STAGE

#pragma unroll
    for (int mi = 0; mi < 4; mi++) {
        int r = m0 + wm * 64 + mi * 16 + gid;
#pragma unroll
        for (int ni = 0; ni < 4; ni++) {
            int c = n0 + wn * 32 + ni * 8 + tig * 2;
            *(float2*)&Cb[(size_t)r * EMB + c] = make_float2(acc[mi][ni][0], acc[mi][ni][1]);
            *(float2*)&Cb[(size_t)(r + 8) * EMB + c] = make_float2(acc[mi][ni][2], acc[mi][ni][3]);
        }
    }
}

// ---------------------------------------------------------------------------
// Launch. Inputs: Xin_q, Xin_k, Xin_v, mask, Wq, Wk, Wv.
// Output: z [8,2048,512] then attn_p [8,2048,2048], fp32.
// ---------------------------------------------------------------------------
extern "C" void kernel_launch(void* const* d_in, const int* in_sizes, int n_in,
                              void* d_out, int out_size)
{
    const float* Xq = (const float*)d_in[0];
    const float* Xk = (const float*)d_in[1];
    const float* Xv = (const float*)d_in[2];
    const int*   mk = (const int*)d_in[3];
    const float* Wq = (const float*)d_in[4];
    const float* Wk = (const float*)d_in[5];
    const float* Wv = (const float*)d_in[6];

    float* out_z = (float*)d_out;
    float* out_p = out_z + (size_t)BATCH * SEQ * EMB;

    const float inv_scale = 0.21022410381342864f;  // 1/512^(1/4)

    const int SC_SMEM = STAGES * (128 * 36 + 128 * 36) * 4;   // 110592 B
    const int PV_SMEM = STAGES * (128 * 36 + 32 * 136) * 4;   // 107520 B
    cudaFuncSetAttribute(scores_kernel, cudaFuncAttributeMaxDynamicSharedMemorySize, SC_SMEM);
    cudaFuncSetAttribute(pv_kernel, cudaFuncAttributeMaxDynamicSharedMemorySize, PV_SMEM);

    proj_kernel<<<dim3(EMB / BN, BSZ / BM, 3), 256>>>(Xq, Xk, Xv, Wq, Wk, Wv, inv_scale);
    scores_kernel<<<dim3(SEQ / BN, SEQ / BM, BATCH), 256, SC_SMEM>>>(mk, out_p);
    softmax_kernel<<<BSZ, 256>>>(out_p);
    pv_kernel<<<dim3(EMB / BN, SEQ / BM, BATCH), 256, PV_SMEM>>>(out_p, out_z);
}

// round 11
// speedup vs baseline: 1.9268x; 1.0486x over previous
#include <cuda_runtime.h>
#include <math.h>
#include <stdint.h>

#define NEGINF -1000000.0f

// Problem constants
#define BATCH 8
#define SEQ   2048
#define EMB   512
#define BSZ   (BATCH * SEQ)

// Scratch (no allocs allowed). tf32-rounded fp32 bit patterns.
// g_Q, g_K: [b][s][e] row-major. g_V: TRANSPOSED per batch: [b][e][s].
__device__ float g_Q[(size_t)BSZ * EMB];
__device__ float g_K[(size_t)BSZ * EMB];
__device__ float g_V[(size_t)BSZ * EMB];

#define BM 128
#define BN 128
#define BK 32          // scores/pv chunk
#define STAGES 3       // ring depth, prefetch distance 2
#define ROWW 36        // smem row stride in words (36*4=144B; 4 mod 32 banks)
#define ROWB 144
#define TILEB (128 * ROWB)   // one operand stage: 18432 B

__device__ __forceinline__ uint32_t f2tf(float f) {
    uint32_t r;
    asm("cvt.rna.tf32.f32 %0, %1;" : "=r"(r) : "f"(f));
    return r;
}
__device__ __forceinline__ float f2tf_f(float f) { return __uint_as_float(f2tf(f)); }

__device__ __forceinline__ void mma_tf32(float (&d)[4], const uint32_t (&a)[4],
                                         const uint32_t (&b)[2]) {
    asm volatile(
        "mma.sync.aligned.m16n8k8.row.col.f32.tf32.tf32.f32 "
        "{%0,%1,%2,%3}, {%4,%5,%6,%7}, {%8,%9}, {%0,%1,%2,%3};\n"
        : "+f"(d[0]), "+f"(d[1]), "+f"(d[2]), "+f"(d[3])
        : "r"(a[0]), "r"(a[1]), "r"(a[2]), "r"(a[3]), "r"(b[0]), "r"(b[1]));
}

#define LDSM_X4(r0, r1, r2, r3, addr)                                        \
    asm volatile("ldmatrix.sync.aligned.m8n8.x4.shared.b16 {%0,%1,%2,%3}, [%4];" \
                 : "=r"(r0), "=r"(r1), "=r"(r2), "=r"(r3) : "r"(addr))

__device__ __forceinline__ void cp16(const void* dst_smem, const void* src) {
    uint32_t d = (uint32_t)__cvta_generic_to_shared(dst_smem);
    asm volatile("cp.async.cg.shared.global [%0], [%1], 16;" :: "r"(d), "l"(src));
}
#define CP_COMMIT() asm volatile("cp.async.commit_group;" ::: "memory")
#define CP_WAIT1()  asm volatile("cp.async.wait_group 1;" ::: "memory")

// ---------------------------------------------------------------------------
// Kernel 1: projections (register-pipelined BK=16). For z==2 (V) the epilogue
// writes TRANSPOSED per batch so pv can ldmatrix its B operand.
// ---------------------------------------------------------------------------
__global__ __launch_bounds__(256, 2)
void proj_kernel(const float* __restrict__ Xq, const float* __restrict__ Xk,
                 const float* __restrict__ Xv, const float* __restrict__ Wq,
                 const float* __restrict__ Wk, const float* __restrict__ Wv,
                 float inv_scale)
{
    const float* A; const float* W; float* C; float alpha;
    int z = blockIdx.z;
    if (z == 0)      { A = Xq; W = Wq; C = g_Q; alpha = inv_scale; }
    else if (z == 1) { A = Xk; W = Wk; C = g_K; alpha = inv_scale; }
    else             { A = Xv; W = Wv; C = g_V; alpha = 1.0f; }

    const int K = 512, N = 512;
    const int PBK = 16;

    __shared__ uint32_t As[2][PBK][BM + 4];
    __shared__ uint32_t Bs[2][PBK][BN + 4];

    int tid = threadIdx.x;
    int wid = tid >> 5, lane = tid & 31;
    int gid = lane >> 2, tig = lane & 3;
    int wm = wid >> 2, wn = wid & 3;
    int m0 = blockIdx.y * BM, n0 = blockIdx.x * BN;

    int arow = tid >> 2;
    int acol = (tid & 3) << 2;
    int brow = tid >> 5;
    int bcol = (tid & 31) << 2;

    float acc[4][4][4];
#pragma unroll
    for (int i = 0; i < 4; i++)
#pragma unroll
        for (int j = 0; j < 4; j++)
#pragma unroll
            for (int r = 0; r < 4; r++) acc[i][j][r] = 0.f;

    float4 ra[2], rb[2];
#define PROJ_LDG(k0)                                                          \
    do {                                                                      \
        ra[0] = *(const float4*)&A[(size_t)(m0 + arow) * K + (k0) + acol];    \
        ra[1] = *(const float4*)&A[(size_t)(m0 + arow + 64) * K + (k0) + acol]; \
        rb[0] = *(const float4*)&W[(size_t)((k0) + brow) * N + n0 + bcol];    \
        rb[1] = *(const float4*)&W[(size_t)((k0) + brow + 8) * N + n0 + bcol]; \
    } while (0)
#define PROJ_STS(buf)                                                         \
    do {                                                                      \
        _Pragma("unroll")                                                     \
        for (int p = 0; p < 2; p++) {                                         \
            As[buf][acol + 0][arow + p * 64] = f2tf(ra[p].x);                 \
            As[buf][acol + 1][arow + p * 64] = f2tf(ra[p].y);                 \
            As[buf][acol + 2][arow + p * 64] = f2tf(ra[p].z);                 \
            As[buf][acol + 3][arow + p * 64] = f2tf(ra[p].w);                 \
            uint4 u = make_uint4(f2tf(rb[p].x), f2tf(rb[p].y),                \
                                 f2tf(rb[p].z), f2tf(rb[p].w));               \
            *(uint4*)&Bs[buf][brow + p * 8][bcol] = u;                        \
        }                                                                     \
    } while (0)

    PROJ_LDG(0);
    PROJ_STS(0);
    __syncthreads();

    const int iters = K / PBK;
    for (int it = 0; it < iters; it++) {
        int cur = it & 1;
        bool more = (it + 1 < iters);
        if (more) PROJ_LDG((it + 1) * PBK);
#pragma unroll
        for (int ks = 0; ks < 2; ks++) {
            int kk = ks * 8;
            uint32_t af[4][4], bf[4][2];
#pragma unroll
            for (int mi = 0; mi < 4; mi++) {
                int m = wm * 64 + mi * 16 + gid;
                af[mi][0] = As[cur][kk + tig][m];
                af[mi][1] = As[cur][kk + tig][m + 8];
                af[mi][2] = As[cur][kk + tig + 4][m];
                af[mi][3] = As[cur][kk + tig + 4][m + 8];
            }
#pragma unroll
            for (int ni = 0; ni < 4; ni++) {
                int n = wn * 32 + ni * 8 + gid;
                bf[ni][0] = Bs[cur][kk + tig][n];
                bf[ni][1] = Bs[cur][kk + tig + 4][n];
            }
#pragma unroll
            for (int mi = 0; mi < 4; mi++)
#pragma unroll
                for (int ni = 0; ni < 4; ni++)
                    mma_tf32(acc[mi][ni], af[mi], bf[ni]);
        }
        if (more) PROJ_STS(cur ^ 1);
        __syncthreads();
    }
#undef PROJ_LDG
#undef PROJ_STS

    if (z != 2) {
#pragma unroll
        for (int mi = 0; mi < 4; mi++) {
            int r = m0 + wm * 64 + mi * 16 + gid;
#pragma unroll
            for (int ni = 0; ni < 4; ni++) {
                int c = n0 + wn * 32 + ni * 8 + tig * 2;
                *(float2*)&C[(size_t)r * N + c] =
                    make_float2(f2tf_f(acc[mi][ni][0] * alpha), f2tf_f(acc[mi][ni][1] * alpha));
                *(float2*)&C[(size_t)(r + 8) * N + c] =
                    make_float2(f2tf_f(acc[mi][ni][2] * alpha), f2tf_f(acc[mi][ni][3] * alpha));
            }
        }
    } else {
        // V transposed: [b][e][s]; r -> (batch, s), c -> e.
        int bb = m0 >> 11;                 // batch (tile never straddles)
        float* Vb = C + (size_t)bb * SEQ * EMB;
#pragma unroll
        for (int mi = 0; mi < 4; mi++) {
            int s = (m0 & 2047) + wm * 64 + mi * 16 + gid;
#pragma unroll
            for (int ni = 0; ni < 4; ni++) {
                int c = n0 + wn * 32 + ni * 8 + tig * 2;
                Vb[(size_t)c * SEQ + s]           = f2tf_f(acc[mi][ni][0]);
                Vb[(size_t)(c + 1) * SEQ + s]     = f2tf_f(acc[mi][ni][1]);
                Vb[(size_t)c * SEQ + s + 8]       = f2tf_f(acc[mi][ni][2]);
                Vb[(size_t)(c + 1) * SEQ + s + 8] = f2tf_f(acc[mi][ni][3]);
            }
        }
    }
}

// ---------------------------------------------------------------------------
// Shared GEMM core for scores/pv: both operands in [row][ROWW] smem tiles,
// ldmatrix fragment loads, BK=32, 3-stage ring.
// Fragment address bases (per thread):
//   A: row = wm*64 + (lane&15), col16 = (lane>>4)        [mi stride 16 rows]
//   B: row = wn*32 + ((lane>>4)<<3) + (lane&7), col16 = (lane>>3)&1
// ---------------------------------------------------------------------------
#define GEMM_FRAG_COMPUTE(aBase, bBase, curOff)                              \
    do {                                                                     \
        _Pragma("unroll")                                                    \
        for (int ks = 0; ks < 4; ks++) {                                     \
            uint32_t af[4][4], bf[4][2];                                     \
            _Pragma("unroll")                                                \
            for (int mi = 0; mi < 4; mi++)                                   \
                LDSM_X4(af[mi][0], af[mi][1], af[mi][2], af[mi][3],          \
                        (aBase) + (curOff) + mi * (16 * ROWB) + ks * 32);    \
            _Pragma("unroll")                                                \
            for (int np = 0; np < 2; np++)                                   \
                LDSM_X4(bf[2 * np][0], bf[2 * np][1],                        \
                        bf[2 * np + 1][0], bf[2 * np + 1][1],                \
                        (bBase) + (curOff) + np * (16 * ROWB) + ks * 32);    \
            _Pragma("unroll")                                                \
            for (int mi = 0; mi < 4; mi++)                                   \
                _Pragma("unroll")                                            \
                for (int ni = 0; ni < 4; ni++)                               \
                    mma_tf32(acc[mi][ni], af[mi], bf[ni]);                   \
        }                                                                    \
    } while (0)

// ---------------------------------------------------------------------------
// Kernel 2: masked scores. Q,K both [row][k] tiles.
// Dynamic smem: 2 * STAGES * TILEB = 110592 B.
// ---------------------------------------------------------------------------
__global__ __launch_bounds__(256, 2)
void scores_kernel(const int* __restrict__ mask, float* __restrict__ out_p)
{
    extern __shared__ uint32_t dsm[];
    uint32_t (*Qs)[128][ROWW] = (uint32_t (*)[128][ROWW])dsm;
    uint32_t (*Ks)[128][ROWW] = (uint32_t (*)[128][ROWW])(dsm + STAGES * 128 * ROWW);

    int b = blockIdx.z;
    const float* Qb = g_Q + (size_t)b * SEQ * EMB;
    const float* Kb = g_K + (size_t)b * SEQ * EMB;
    const int*  Mb  = mask + (size_t)b * SEQ * SEQ;
    float*      Cb  = out_p + (size_t)b * SEQ * SEQ;

    int tid = threadIdx.x;
    int wid = tid >> 5, lane = tid & 31;
    int gid = lane >> 2, tig = lane & 3;
    int wm = wid >> 2, wn = wid & 3;
    int m0 = blockIdx.y * BM, n0 = blockIdx.x * BN;

    int srow = tid >> 3;            // 0..31
    int sseg = (tid & 7) << 2;      // 0..28

    uint32_t smem_u32 = (uint32_t)__cvta_generic_to_shared(dsm);
    uint32_t aBase = smem_u32 + (uint32_t)(wm * 64 + (lane & 15)) * ROWB + ((lane >> 4) << 4);
    uint32_t bBase = smem_u32 + (uint32_t)(STAGES * TILEB)
                   + (uint32_t)(wn * 32 + ((lane >> 4) << 3) + (lane & 7)) * ROWB
                   + (((lane >> 3) & 1) << 4);

    float acc[4][4][4];
#pragma unroll
    for (int i = 0; i < 4; i++)
#pragma unroll
        for (int j = 0; j < 4; j++)
#pragma unroll
            for (int r = 0; r < 4; r++) acc[i][j][r] = 0.f;

#define SC_STAGE(buf, k0)                                                     \
    do {                                                                      \
        _Pragma("unroll")                                                     \
        for (int p = 0; p < 4; p++) {                                         \
            cp16(&Qs[buf][p * 32 + srow][sseg],                               \
                 &Qb[(size_t)(m0 + p * 32 + srow) * EMB + (k0) + sseg]);      \
            cp16(&Ks[buf][p * 32 + srow][sseg],                               \
                 &Kb[(size_t)(n0 + p * 32 + srow) * EMB + (k0) + sseg]);      \
        }                                                                     \
        CP_COMMIT();                                                          \
    } while (0)

    const int iters = EMB / BK;   // 16
    SC_STAGE(0, 0);
    SC_STAGE(1, BK);

    int cur = 0, wr = 2;
    for (int it = 0; it < iters; it++) {
        CP_WAIT1();
        __syncthreads();
        if (it + 2 < iters) SC_STAGE(wr, (it + 2) * BK);
        else CP_COMMIT();
        uint32_t curOff = (uint32_t)cur * TILEB;
        GEMM_FRAG_COMPUTE(aBase, bBase, curOff);
        cur = (cur == STAGES - 1) ? 0 : cur + 1;
        wr  = (wr  == STAGES - 1) ? 0 : wr + 1;
    }
#undef SC_STAGE

#pragma unroll
    for (int mi = 0; mi < 4; mi++) {
        int r = m0 + wm * 64 + mi * 16 + gid;
#pragma unroll
        for (int ni = 0; ni < 4; ni++) {
            int c = n0 + wn * 32 + ni * 8 + tig * 2;
            size_t o0 = (size_t)r * SEQ + c;
            size_t o1 = (size_t)(r + 8) * SEQ + c;
            int2 mv0 = *(const int2*)&Mb[o0];
            int2 mv1 = *(const int2*)&Mb[o1];
            *(float2*)&Cb[o0] = make_float2(mv0.x ? acc[mi][ni][0] : NEGINF,
                                            mv0.y ? acc[mi][ni][1] : NEGINF);
            *(float2*)&Cb[o1] = make_float2(mv1.x ? acc[mi][ni][2] : NEGINF,
                                            mv1.y ? acc[mi][ni][3] : NEGINF);
        }
    }
}

// ---------------------------------------------------------------------------
// Kernel 3: row softmax (in place). Masked = NEGINF -> exactly 0.
// Outputs tf32-rounded so pv can byte-copy.
// ---------------------------------------------------------------------------
__global__ __launch_bounds__(256)
void softmax_kernel(float* __restrict__ P)
{
    float* prow = P + (size_t)blockIdx.x * SEQ;
    int tid = threadIdx.x;
    int lane = tid & 31, warp = tid >> 5;
    __shared__ float red[8];

    float4 v0 = ((const float4*)prow)[tid];
    float4 v1 = ((const float4*)prow)[tid + 256];
    float x[8] = {v0.x, v0.y, v0.z, v0.w, v1.x, v1.y, v1.z, v1.w};

    float m = x[0];
#pragma unroll
    for (int i = 1; i < 8; i++) m = fmaxf(m, x[i]);
#pragma unroll
    for (int o = 16; o > 0; o >>= 1) m = fmaxf(m, __shfl_xor_sync(0xFFFFFFFFu, m, o));
    if (lane == 0) red[warp] = m;
    __syncthreads();
    m = red[0];
#pragma unroll
    for (int i = 1; i < 8; i++) m = fmaxf(m, red[i]);

    if (m == NEGINF) {  // fully masked row
        float4 zz = make_float4(0.f, 0.f, 0.f, 0.f);
        ((float4*)prow)[tid] = zz;
        ((float4*)prow)[tid + 256] = zz;
        return;
    }

    float e[8], s = 0.f;
#pragma unroll
    for (int i = 0; i < 8; i++) { e[i] = __expf(x[i] - m); s += e[i]; }
#pragma unroll
    for (int o = 16; o > 0; o >>= 1) s += __shfl_xor_sync(0xFFFFFFFFu, s, o);
    __syncthreads();
    if (lane == 0) red[warp] = s;
    __syncthreads();
    s = 0.f;
#pragma unroll
    for (int i = 0; i < 8; i++) s += red[i];
    float inv = 1.0f / s;

    ((float4*)prow)[tid] = make_float4(f2tf_f(e[0] * inv), f2tf_f(e[1] * inv),
                                       f2tf_f(e[2] * inv), f2tf_f(e[3] * inv));
    ((float4*)prow)[tid + 256] = make_float4(f2tf_f(e[4] * inv), f2tf_f(e[5] * inv),
                                             f2tf_f(e[6] * inv), f2tf_f(e[7] * inv));
}

// ---------------------------------------------------------------------------
// Kernel 4: z = P @ V. A = P rows [q][k]; B = Vt rows [e][s] (K-major), so the
// structure is identical to scores. Dynamic smem: 110592 B.
// ---------------------------------------------------------------------------
__global__ __launch_bounds__(256, 2)
void pv_kernel(const float* __restrict__ P, float* __restrict__ out_z)
{
    extern __shared__ uint32_t dsm[];
    uint32_t (*As)[128][ROWW] = (uint32_t (*)[128][ROWW])dsm;
    uint32_t (*Bs)[128][ROWW] = (uint32_t (*)[128][ROWW])(dsm + STAGES * 128 * ROWW);

    int b = blockIdx.z;
    const float* Ab = P + (size_t)b * SEQ * SEQ;
    const float* Vt = g_V + (size_t)b * SEQ * EMB;   // [e][s]
    float*       Cb = out_z + (size_t)b * SEQ * EMB;

    int tid = threadIdx.x;
    int wid = tid >> 5, lane = tid & 31;
    int gid = lane >> 2, tig = lane & 3;
    int wm = wid >> 2, wn = wid & 3;
    int m0 = blockIdx.y * BM, n0 = blockIdx.x * BN;

    int srow = tid >> 3;
    int sseg = (tid & 7) << 2;

    uint32_t smem_u32 = (uint32_t)__cvta_generic_to_shared(dsm);
    uint32_t aBase = smem_u32 + (uint32_t)(wm * 64 + (lane & 15)) * ROWB + ((lane >> 4) << 4);
    uint32_t bBase = smem_u32 + (uint32_t)(STAGES * TILEB)
                   + (uint32_t)(wn * 32 + ((lane >> 4) << 3) + (lane & 7)) * ROWB
                   + (((lane >> 3) & 1) << 4);

    float acc[4][4][4];
#pragma unroll
    for (int i = 0; i < 4; i++)
#pragma unroll
        for (int j = 0; j < 4; j++)
#pragma unroll
            for (int r = 0; r < 4; r++) acc[i][j][r] = 0.f;

#define PV_STAGE(buf, k0)                                                     \
    do {                                                                      \
        _Pragma("unroll")                                                     \
        for (int p = 0; p < 4; p++) {                                         \
            cp16(&As[buf][p * 32 + srow][sseg],                               \
                 &Ab[(size_t)(m0 + p * 32 + srow) * SEQ + (k0) + sseg]);      \
            cp16(&Bs[buf][p * 32 + srow][sseg],                               \
                 &Vt[(size_t)(n0 + p * 32 + srow) * SEQ + (k0) + sseg]);      \
        }                                                                     \
        CP_COMMIT();                                                          \
    } while (0)

    const int iters = SEQ / BK;   // 64
    PV_STAGE(0, 0);
    PV_STAGE(1, BK);

    int cur = 0, wr = 2;
    for (int it = 0; it < iters; it++) {
        CP_WAIT1();
        __syncthreads();
        if (it + 2 < iters) PV_STAGE(wr, (it + 2) * BK);
        else CP_COMMIT();
        uint32_t curOff = (uint32_t)cur * TILEB;
        GEMM_FRAG_COMPUTE(aBase, bBase, curOff);
        cur = (cur == STAGES - 1) ? 0 : cur + 1;
        wr  = (wr  == STAGES - 1) ? 0 : wr + 1;
    }
#undef PV_STAGE

#pragma unroll
    for (int mi = 0; mi < 4; mi++) {
        int r = m0 + wm * 64 + mi * 16 + gid;
#pragma unroll
        for (int ni = 0; ni < 4; ni++) {
            int c = n0 + wn * 32 + ni * 8 + tig * 2;
            *(float2*)&Cb[(size_t)r * EMB + c] = make_float2(acc[mi][ni][0], acc[mi][ni][1]);
            *(float2*)&Cb[(size_t)(r + 8) * EMB + c] = make_float2(acc[mi][ni][2], acc[mi][ni][3]);
        }
    }
}

// ---------------------------------------------------------------------------
// Launch. Inputs: Xin_q, Xin_k, Xin_v, mask, Wq, Wk, Wv.
// Output: z [8,2048,512] then attn_p [8,2048,2048], fp32.
// ---------------------------------------------------------------------------
extern "C" void kernel_launch(void* const* d_in, const int* in_sizes, int n_in,
                              void* d_out, int out_size)
{
    const float* Xq = (const float*)d_in[0];
    const float* Xk = (const float*)d_in[1];
    const float* Xv = (const float*)d_in[2];
    const int*   mk = (const int*)d_in[3];
    const float* Wq = (const float*)d_in[4];
    const float* Wk = (const float*)d_in[5];
    const float* Wv = (const float*)d_in[6];

    float* out_z = (float*)d_out;
    float* out_p = out_z + (size_t)BATCH * SEQ * EMB;

    const float inv_scale = 0.21022410381342864f;  // 1/512^(1/4)

    const int GEMM_SMEM = 2 * STAGES * TILEB;   // 110592 B
    cudaFuncSetAttribute(scores_kernel, cudaFuncAttributeMaxDynamicSharedMemorySize, GEMM_SMEM);
    cudaFuncSetAttribute(pv_kernel, cudaFuncAttributeMaxDynamicSharedMemorySize, GEMM_SMEM);

    proj_kernel<<<dim3(EMB / BN, BSZ / BM, 3), 256>>>(Xq, Xk, Xv, Wq, Wk, Wv, inv_scale);
    scores_kernel<<<dim3(SEQ / BN, SEQ / BM, BATCH), 256, GEMM_SMEM>>>(mk, out_p);
    softmax_kernel<<<BSZ, 256>>>(out_p);
    pv_kernel<<<dim3(EMB / BN, SEQ / BM, BATCH), 256, GEMM_SMEM>>>(out_p, out_z);
}

// round 12
// speedup vs baseline: 2.5521x; 1.3245x over previous
#include <cuda_runtime.h>
#include <cuda_fp16.h>
#include <math.h>
#include <stdint.h>

#define NEGINF -1000000.0f

// Problem constants
#define BATCH 8
#define SEQ   2048
#define EMB   512
#define BSZ   (BATCH * SEQ)

// Scratch (no allocs allowed).
// g_Q, g_K: fp16 [b][s][e]. g_V: fp16 TRANSPOSED per batch [b][e][s].
// g_P16: fp16 copy of softmax(P) for pv's A operand.
__device__ __half g_Q[(size_t)BSZ * EMB];
__device__ __half g_K[(size_t)BSZ * EMB];
__device__ __half g_V[(size_t)BSZ * EMB];
__device__ __half g_P16[(size_t)BATCH * SEQ * SEQ];

#define BM 128
#define BN 128
#define BKH 64         // scores/pv k-chunk in (fp16) elements; 128B per row
#define STAGES 3       // ring depth, prefetch distance 2
#define ROWB 144       // smem row stride bytes (128B data + 16B pad; bank walk 4)
#define TILEB (128 * ROWB)   // one operand stage: 18432 B

__device__ __forceinline__ uint32_t f2tf(float f) {
    uint32_t r;
    asm("cvt.rna.tf32.f32 %0, %1;" : "=r"(r) : "f"(f));
    return r;
}

__device__ __forceinline__ void mma_tf32(float (&d)[4], const uint32_t (&a)[4],
                                         const uint32_t (&b)[2]) {
    asm volatile(
        "mma.sync.aligned.m16n8k8.row.col.f32.tf32.tf32.f32 "
        "{%0,%1,%2,%3}, {%4,%5,%6,%7}, {%8,%9}, {%0,%1,%2,%3};\n"
        : "+f"(d[0]), "+f"(d[1]), "+f"(d[2]), "+f"(d[3])
        : "r"(a[0]), "r"(a[1]), "r"(a[2]), "r"(a[3]), "r"(b[0]), "r"(b[1]));
}

__device__ __forceinline__ void mma_f16(float (&d)[4], const uint32_t (&a)[4],
                                        const uint32_t (&b)[2]) {
    asm volatile(
        "mma.sync.aligned.m16n8k16.row.col.f32.f16.f16.f32 "
        "{%0,%1,%2,%3}, {%4,%5,%6,%7}, {%8,%9}, {%0,%1,%2,%3};\n"
        : "+f"(d[0]), "+f"(d[1]), "+f"(d[2]), "+f"(d[3])
        : "r"(a[0]), "r"(a[1]), "r"(a[2]), "r"(a[3]), "r"(b[0]), "r"(b[1]));
}

#define LDSM_X4(r0, r1, r2, r3, addr)                                        \
    asm volatile("ldmatrix.sync.aligned.m8n8.x4.shared.b16 {%0,%1,%2,%3}, [%4];" \
                 : "=r"(r0), "=r"(r1), "=r"(r2), "=r"(r3) : "r"(addr))

__device__ __forceinline__ void cp16(const void* dst_smem, const void* src) {
    uint32_t d = (uint32_t)__cvta_generic_to_shared(dst_smem);
    asm volatile("cp.async.cg.shared.global [%0], [%1], 16;" :: "r"(d), "l"(src));
}
#define CP_COMMIT() asm volatile("cp.async.commit_group;" ::: "memory")
#define CP_WAIT1()  asm volatile("cp.async.wait_group 1;" ::: "memory")

// ---------------------------------------------------------------------------
// Kernel 1: projections (register-pipelined tf32 GEMM over fp32 inputs).
// Epilogue emits fp16: Q,K row-major; V transposed per batch [e][s].
// ---------------------------------------------------------------------------
__global__ __launch_bounds__(256, 2)
void proj_kernel(const float* __restrict__ Xq, const float* __restrict__ Xk,
                 const float* __restrict__ Xv, const float* __restrict__ Wq,
                 const float* __restrict__ Wk, const float* __restrict__ Wv,
                 float inv_scale)
{
    const float* A; const float* W; __half* C; float alpha;
    int z = blockIdx.z;
    if (z == 0)      { A = Xq; W = Wq; C = g_Q; alpha = inv_scale; }
    else if (z == 1) { A = Xk; W = Wk; C = g_K; alpha = inv_scale; }
    else             { A = Xv; W = Wv; C = g_V; alpha = 1.0f; }

    const int K = 512, N = 512;
    const int PBK = 16;

    __shared__ uint32_t As[2][PBK][BM + 4];
    __shared__ uint32_t Bs[2][PBK][BN + 4];

    int tid = threadIdx.x;
    int wid = tid >> 5, lane = tid & 31;
    int gid = lane >> 2, tig = lane & 3;
    int wm = wid >> 2, wn = wid & 3;
    int m0 = blockIdx.y * BM, n0 = blockIdx.x * BN;

    int arow = tid >> 2;
    int acol = (tid & 3) << 2;
    int brow = tid >> 5;
    int bcol = (tid & 31) << 2;

    float acc[4][4][4];
#pragma unroll
    for (int i = 0; i < 4; i++)
#pragma unroll
        for (int j = 0; j < 4; j++)
#pragma unroll
            for (int r = 0; r < 4; r++) acc[i][j][r] = 0.f;

    float4 ra[2], rb[2];
#define PROJ_LDG(k0)                                                          \
    do {                                                                      \
        ra[0] = *(const float4*)&A[(size_t)(m0 + arow) * K + (k0) + acol];    \
        ra[1] = *(const float4*)&A[(size_t)(m0 + arow + 64) * K + (k0) + acol]; \
        rb[0] = *(const float4*)&W[(size_t)((k0) + brow) * N + n0 + bcol];    \
        rb[1] = *(const float4*)&W[(size_t)((k0) + brow + 8) * N + n0 + bcol]; \
    } while (0)
#define PROJ_STS(buf)                                                         \
    do {                                                                      \
        _Pragma("unroll")                                                     \
        for (int p = 0; p < 2; p++) {                                         \
            As[buf][acol + 0][arow + p * 64] = f2tf(ra[p].x);                 \
            As[buf][acol + 1][arow + p * 64] = f2tf(ra[p].y);                 \
            As[buf][acol + 2][arow + p * 64] = f2tf(ra[p].z);                 \
            As[buf][acol + 3][arow + p * 64] = f2tf(ra[p].w);                 \
            uint4 u = make_uint4(f2tf(rb[p].x), f2tf(rb[p].y),                \
                                 f2tf(rb[p].z), f2tf(rb[p].w));               \
            *(uint4*)&Bs[buf][brow + p * 8][bcol] = u;                        \
        }                                                                     \
    } while (0)

    PROJ_LDG(0);
    PROJ_STS(0);
    __syncthreads();

    const int iters = K / PBK;
    for (int it = 0; it < iters; it++) {
        int cur = it & 1;
        bool more = (it + 1 < iters);
        if (more) PROJ_LDG((it + 1) * PBK);
#pragma unroll
        for (int ks = 0; ks < 2; ks++) {
            int kk = ks * 8;
            uint32_t af[4][4], bf[4][2];
#pragma unroll
            for (int mi = 0; mi < 4; mi++) {
                int m = wm * 64 + mi * 16 + gid;
                af[mi][0] = As[cur][kk + tig][m];
                af[mi][1] = As[cur][kk + tig][m + 8];
                af[mi][2] = As[cur][kk + tig + 4][m];
                af[mi][3] = As[cur][kk + tig + 4][m + 8];
            }
#pragma unroll
            for (int ni = 0; ni < 4; ni++) {
                int n = wn * 32 + ni * 8 + gid;
                bf[ni][0] = Bs[cur][kk + tig][n];
                bf[ni][1] = Bs[cur][kk + tig + 4][n];
            }
#pragma unroll
            for (int mi = 0; mi < 4; mi++)
#pragma unroll
                for (int ni = 0; ni < 4; ni++)
                    mma_tf32(acc[mi][ni], af[mi], bf[ni]);
        }
        if (more) PROJ_STS(cur ^ 1);
        __syncthreads();
    }
#undef PROJ_LDG
#undef PROJ_STS

    if (z != 2) {
#pragma unroll
        for (int mi = 0; mi < 4; mi++) {
            int r = m0 + wm * 64 + mi * 16 + gid;
#pragma unroll
            for (int ni = 0; ni < 4; ni++) {
                int c = n0 + wn * 32 + ni * 8 + tig * 2;
                *(__half2*)&C[(size_t)r * N + c] =
                    __floats2half2_rn(acc[mi][ni][0] * alpha, acc[mi][ni][1] * alpha);
                *(__half2*)&C[(size_t)(r + 8) * N + c] =
                    __floats2half2_rn(acc[mi][ni][2] * alpha, acc[mi][ni][3] * alpha);
            }
        }
    } else {
        // V transposed: [b][e][s]
        int bb = m0 >> 11;
        __half* Vb = C + (size_t)bb * SEQ * EMB;
#pragma unroll
        for (int mi = 0; mi < 4; mi++) {
            int s = (m0 & 2047) + wm * 64 + mi * 16 + gid;
#pragma unroll
            for (int ni = 0; ni < 4; ni++) {
                int c = n0 + wn * 32 + ni * 8 + tig * 2;
                Vb[(size_t)c * SEQ + s]           = __float2half_rn(acc[mi][ni][0]);
                Vb[(size_t)(c + 1) * SEQ + s]     = __float2half_rn(acc[mi][ni][1]);
                Vb[(size_t)c * SEQ + s + 8]       = __float2half_rn(acc[mi][ni][2]);
                Vb[(size_t)(c + 1) * SEQ + s + 8] = __float2half_rn(acc[mi][ni][3]);
            }
        }
    }
}

// ---------------------------------------------------------------------------
// Shared fp16 GEMM core (scores/pv): both operands [row][128B+pad] smem tiles,
// ldmatrix b16 fragments, k-chunk 64 halves, 3-stage cp.async ring.
// Base address formulas identical to the validated round-11 layout.
// ---------------------------------------------------------------------------
#define GEMM_FRAG_COMPUTE_F16(aBase, bBase, curOff)                          \
    do {                                                                     \
        _Pragma("unroll")                                                    \
        for (int ks = 0; ks < 4; ks++) {                                     \
            uint32_t af[4][4], bf[4][2];                                     \
            _Pragma("unroll")                                                \
            for (int mi = 0; mi < 4; mi++)                                   \
                LDSM_X4(af[mi][0], af[mi][1], af[mi][2], af[mi][3],          \
                        (aBase) + (curOff) + mi * (16 * ROWB) + ks * 32);    \
            _Pragma("unroll")                                                \
            for (int np = 0; np < 2; np++)                                   \
                LDSM_X4(bf[2 * np][0], bf[2 * np][1],                        \
                        bf[2 * np + 1][0], bf[2 * np + 1][1],                \
                        (bBase) + (curOff) + np * (16 * ROWB) + ks * 32);    \
            _Pragma("unroll")                                                \
            for (int mi = 0; mi < 4; mi++)                                   \
                _Pragma("unroll")                                            \
                for (int ni = 0; ni < 4; ni++)                               \
                    mma_f16(acc[mi][ni], af[mi], bf[ni]);                    \
        }                                                                    \
    } while (0)

// ---------------------------------------------------------------------------
// Kernel 2: masked scores. Q,K fp16 [row][k] tiles. iters = 512/64 = 8.
// Dynamic smem: 2 * STAGES * TILEB = 110592 B.
// ---------------------------------------------------------------------------
__global__ __launch_bounds__(256, 2)
void scores_kernel(const int* __restrict__ mask, float* __restrict__ out_p)
{
    extern __shared__ char dsm[];

    int b = blockIdx.z;
    const __half* Qb = g_Q + (size_t)b * SEQ * EMB;
    const __half* Kb = g_K + (size_t)b * SEQ * EMB;
    const int*   Mb  = mask + (size_t)b * SEQ * SEQ;
    float*       Cb  = out_p + (size_t)b * SEQ * SEQ;

    int tid = threadIdx.x;
    int wid = tid >> 5, lane = tid & 31;
    int gid = lane >> 2, tig = lane & 3;
    int wm = wid >> 2, wn = wid & 3;
    int m0 = blockIdx.y * BM, n0 = blockIdx.x * BN;

    int srow = tid >> 3;            // 0..31
    int ssegB = (tid & 7) << 4;     // byte seg 0..112
    int ssegH = (tid & 7) << 3;     // half seg 0..56

    uint32_t smem_u32 = (uint32_t)__cvta_generic_to_shared(dsm);
    uint32_t aBase = smem_u32 + (uint32_t)(wm * 64 + (lane & 15)) * ROWB + ((lane >> 4) << 4);
    uint32_t bBase = smem_u32 + (uint32_t)(STAGES * TILEB)
                   + (uint32_t)(wn * 32 + ((lane >> 4) << 3) + (lane & 7)) * ROWB
                   + (((lane >> 3) & 1) << 4);

    float acc[4][4][4];
#pragma unroll
    for (int i = 0; i < 4; i++)
#pragma unroll
        for (int j = 0; j < 4; j++)
#pragma unroll
            for (int r = 0; r < 4; r++) acc[i][j][r] = 0.f;

#define SC_STAGE(buf, k0)                                                     \
    do {                                                                      \
        _Pragma("unroll")                                                     \
        for (int p = 0; p < 4; p++) {                                         \
            int row = p * 32 + srow;                                          \
            cp16(dsm + (buf) * TILEB + row * ROWB + ssegB,                    \
                 &Qb[(size_t)(m0 + row) * EMB + (k0) + ssegH]);               \
            cp16(dsm + STAGES * TILEB + (buf) * TILEB + row * ROWB + ssegB,   \
                 &Kb[(size_t)(n0 + row) * EMB + (k0) + ssegH]);               \
        }                                                                     \
        CP_COMMIT();                                                          \
    } while (0)

    const int iters = EMB / BKH;   // 8
    SC_STAGE(0, 0);
    SC_STAGE(1, BKH);

    int cur = 0, wr = 2;
    for (int it = 0; it < iters; it++) {
        CP_WAIT1();
        __syncthreads();
        if (it + 2 < iters) SC_STAGE(wr, (it + 2) * BKH);
        else CP_COMMIT();
        uint32_t curOff = (uint32_t)cur * TILEB;
        GEMM_FRAG_COMPUTE_F16(aBase, bBase, curOff);
        cur = (cur == STAGES - 1) ? 0 : cur + 1;
        wr  = (wr  == STAGES - 1) ? 0 : wr + 1;
    }
#undef SC_STAGE

#pragma unroll
    for (int mi = 0; mi < 4; mi++) {
        int r = m0 + wm * 64 + mi * 16 + gid;
#pragma unroll
        for (int ni = 0; ni < 4; ni++) {
            int c = n0 + wn * 32 + ni * 8 + tig * 2;
            size_t o0 = (size_t)r * SEQ + c;
            size_t o1 = (size_t)(r + 8) * SEQ + c;
            int2 mv0 = *(const int2*)&Mb[o0];
            int2 mv1 = *(const int2*)&Mb[o1];
            *(float2*)&Cb[o0] = make_float2(mv0.x ? acc[mi][ni][0] : NEGINF,
                                            mv0.y ? acc[mi][ni][1] : NEGINF);
            *(float2*)&Cb[o1] = make_float2(mv1.x ? acc[mi][ni][2] : NEGINF,
                                            mv1.y ? acc[mi][ni][3] : NEGINF);
        }
    }
}

// ---------------------------------------------------------------------------
// Kernel 3: row softmax. Reads fp32 logits; writes fp32 P to d_out (full
// precision) AND fp16 P to g_P16 for pv. Masked = exactly 0 in both.
// ---------------------------------------------------------------------------
__global__ __launch_bounds__(256)
void softmax_kernel(float* __restrict__ P)
{
    float* prow = P + (size_t)blockIdx.x * SEQ;
    __half* prow16 = g_P16 + (size_t)blockIdx.x * SEQ;
    int tid = threadIdx.x;
    int lane = tid & 31, warp = tid >> 5;
    __shared__ float red[8];

    float4 v0 = ((const float4*)prow)[tid];
    float4 v1 = ((const float4*)prow)[tid + 256];
    float x[8] = {v0.x, v0.y, v0.z, v0.w, v1.x, v1.y, v1.z, v1.w};

    float m = x[0];
#pragma unroll
    for (int i = 1; i < 8; i++) m = fmaxf(m, x[i]);
#pragma unroll
    for (int o = 16; o > 0; o >>= 1) m = fmaxf(m, __shfl_xor_sync(0xFFFFFFFFu, m, o));
    if (lane == 0) red[warp] = m;
    __syncthreads();
    m = red[0];
#pragma unroll
    for (int i = 1; i < 8; i++) m = fmaxf(m, red[i]);

    if (m == NEGINF) {  // fully masked row
        float4 zz = make_float4(0.f, 0.f, 0.f, 0.f);
        ((float4*)prow)[tid] = zz;
        ((float4*)prow)[tid + 256] = zz;
        uint2 hz = make_uint2(0u, 0u);
        *(uint2*)&prow16[tid * 4] = hz;
        *(uint2*)&prow16[(tid + 256) * 4] = hz;
        return;
    }

    float e[8], s = 0.f;
#pragma unroll
    for (int i = 0; i < 8; i++) { e[i] = __expf(x[i] - m); s += e[i]; }
#pragma unroll
    for (int o = 16; o > 0; o >>= 1) s += __shfl_xor_sync(0xFFFFFFFFu, s, o);
    __syncthreads();
    if (lane == 0) red[warp] = s;
    __syncthreads();
    s = 0.f;
#pragma unroll
    for (int i = 0; i < 8; i++) s += red[i];
    float inv = 1.0f / s;

    float p0 = e[0] * inv, p1 = e[1] * inv, p2 = e[2] * inv, p3 = e[3] * inv;
    float p4 = e[4] * inv, p5 = e[5] * inv, p6 = e[6] * inv, p7 = e[7] * inv;

    ((float4*)prow)[tid]       = make_float4(p0, p1, p2, p3);
    ((float4*)prow)[tid + 256] = make_float4(p4, p5, p6, p7);

    *(__half2*)&prow16[tid * 4]           = __floats2half2_rn(p0, p1);
    *(__half2*)&prow16[tid * 4 + 2]       = __floats2half2_rn(p2, p3);
    *(__half2*)&prow16[(tid + 256) * 4]     = __floats2half2_rn(p4, p5);
    *(__half2*)&prow16[(tid + 256) * 4 + 2] = __floats2half2_rn(p6, p7);
}

// ---------------------------------------------------------------------------
// Kernel 4: z = P @ V. A = g_P16 [q][k]; B = g_V [e][s] (K-major).
// iters = 2048/64 = 32. Dynamic smem: 110592 B.
// ---------------------------------------------------------------------------
__global__ __launch_bounds__(256, 2)
void pv_kernel(float* __restrict__ out_z)
{
    extern __shared__ char dsm[];

    int b = blockIdx.z;
    const __half* Ab = g_P16 + (size_t)b * SEQ * SEQ;
    const __half* Vt = g_V + (size_t)b * SEQ * EMB;   // [e][s]
    float*        Cb = out_z + (size_t)b * SEQ * EMB;

    int tid = threadIdx.x;
    int wid = tid >> 5, lane = tid & 31;
    int gid = lane >> 2, tig = lane & 3;
    int wm = wid >> 2, wn = wid & 3;
    int m0 = blockIdx.y * BM, n0 = blockIdx.x * BN;

    int srow = tid >> 3;
    int ssegB = (tid & 7) << 4;
    int ssegH = (tid & 7) << 3;

    uint32_t smem_u32 = (uint32_t)__cvta_generic_to_shared(dsm);
    uint32_t aBase = smem_u32 + (uint32_t)(wm * 64 + (lane & 15)) * ROWB + ((lane >> 4) << 4);
    uint32_t bBase = smem_u32 + (uint32_t)(STAGES * TILEB)
                   + (uint32_t)(wn * 32 + ((lane >> 4) << 3) + (lane & 7)) * ROWB
                   + (((lane >> 3) & 1) << 4);

    float acc[4][4][4];
#pragma unroll
    for (int i = 0; i < 4; i++)
#pragma unroll
        for (int j = 0; j < 4; j++)
#pragma unroll
            for (int r = 0; r < 4; r++) acc[i][j][r] = 0.f;

#define PV_STAGE(buf, k0)                                                     \
    do {                                                                      \
        _Pragma("unroll")                                                     \
        for (int p = 0; p < 4; p++) {                                         \
            int row = p * 32 + srow;                                          \
            cp16(dsm + (buf) * TILEB + row * ROWB + ssegB,                    \
                 &Ab[(size_t)(m0 + row) * SEQ + (k0) + ssegH]);               \
            cp16(dsm + STAGES * TILEB + (buf) * TILEB + row * ROWB + ssegB,   \
                 &Vt[(size_t)(n0 + row) * SEQ + (k0) + ssegH]);               \
        }                                                                     \
        CP_COMMIT();                                                          \
    } while (0)

    const int iters = SEQ / BKH;   // 32
    PV_STAGE(0, 0);
    PV_STAGE(1, BKH);

    int cur = 0, wr = 2;
    for (int it = 0; it < iters; it++) {
        CP_WAIT1();
        __syncthreads();
        if (it + 2 < iters) PV_STAGE(wr, (it + 2) * BKH);
        else CP_COMMIT();
        uint32_t curOff = (uint32_t)cur * TILEB;
        GEMM_FRAG_COMPUTE_F16(aBase, bBase, curOff);
        cur = (cur == STAGES - 1) ? 0 : cur + 1;
        wr  = (wr  == STAGES - 1) ? 0 : wr + 1;
    }
#undef PV_STAGE

#pragma unroll
    for (int mi = 0; mi < 4; mi++) {
        int r = m0 + wm * 64 + mi * 16 + gid;
#pragma unroll
        for (int ni = 0; ni < 4; ni++) {
            int c = n0 + wn * 32 + ni * 8 + tig * 2;
            *(float2*)&Cb[(size_t)r * EMB + c] = make_float2(acc[mi][ni][0], acc[mi][ni][1]);
            *(float2*)&Cb[(size_t)(r + 8) * EMB + c] = make_float2(acc[mi][ni][2], acc[mi][ni][3]);
        }
    }
}

// ---------------------------------------------------------------------------
// Launch. Inputs: Xin_q, Xin_k, Xin_v, mask, Wq, Wk, Wv.
// Output: z [8,2048,512] then attn_p [8,2048,2048], fp32.
// ---------------------------------------------------------------------------
extern "C" void kernel_launch(void* const* d_in, const int* in_sizes, int n_in,
                              void* d_out, int out_size)
{
    const float* Xq = (const float*)d_in[0];
    const float* Xk = (const float*)d_in[1];
    const float* Xv = (const float*)d_in[2];
    const int*   mk = (const int*)d_in[3];
    const float* Wq = (const float*)d_in[4];
    const float* Wk = (const float*)d_in[5];
    const float* Wv = (const float*)d_in[6];

    float* out_z = (float*)d_out;
    float* out_p = out_z + (size_t)BATCH * SEQ * EMB;

    const float inv_scale = 0.21022410381342864f;  // 1/512^(1/4)

    const int GEMM_SMEM = 2 * STAGES * TILEB;   // 110592 B
    cudaFuncSetAttribute(scores_kernel, cudaFuncAttributeMaxDynamicSharedMemorySize, GEMM_SMEM);
    cudaFuncSetAttribute(pv_kernel, cudaFuncAttributeMaxDynamicSharedMemorySize, GEMM_SMEM);

    proj_kernel<<<dim3(EMB / BN, BSZ / BM, 3), 256>>>(Xq, Xk, Xv, Wq, Wk, Wv, inv_scale);
    scores_kernel<<<dim3(SEQ / BN, SEQ / BM, BATCH), 256, GEMM_SMEM>>>(mk, out_p);
    softmax_kernel<<<BSZ, 256>>>(out_p);
    pv_kernel<<<dim3(EMB / BN, SEQ / BM, BATCH), 256, GEMM_SMEM>>>(out_z);
}